// round 1
// baseline (speedup 1.0000x reference)
#include <cuda_runtime.h>
#include <math.h>

#define BS   2
#define SEQL 2048
#define DM   1024
#define H    16
#define D    64
#define R    (BS*SEQL)   // 4096

// Scratch: Q/K/V in [b, h, s, d] layout. __device__ globals (no allocation).
__device__ float g_Q[BS*H*SEQL*D];
__device__ float g_K[BS*H*SEQL*D];
__device__ float g_V[BS*H*SEQL*D];

// ---------------------------------------------------------------------------
// Kernel 1: QKV projection.  out[r, o] = (sum_k X[r,k] * W[o,k] + b[o]) * scale
// Both X and W are K-contiguous (NT gemm). Tiled SGEMM 64x64, BK=16,
// 256 threads, 4x4 micro-tile. Writes scattered into [b,h,s,d] layout.
// Q is pre-scaled by 1/sqrt(d) = 0.125 (mask bias is -1e30, so order of
// scaling vs masking is immaterial).
// ---------------------------------------------------------------------------
#define PBM 64
#define PBN 64
#define PBK 16

__global__ __launch_bounds__(256) void qkv_proj_kernel(
    const float* __restrict__ X,
    const float* __restrict__ Wq, const float* __restrict__ bq,
    const float* __restrict__ Wk, const float* __restrict__ bk,
    const float* __restrict__ Wv, const float* __restrict__ bv)
{
    const float* W;
    const float* bias;
    float* Out;
    float scale;
    if (blockIdx.z == 0)      { W = Wq; bias = bq; Out = g_Q; scale = 0.125f; }
    else if (blockIdx.z == 1) { W = Wk; bias = bk; Out = g_K; scale = 1.0f;   }
    else                      { W = Wv; bias = bv; Out = g_V; scale = 1.0f;   }

    __shared__ float As[PBK * PBM];
    __shared__ float Bs[PBK * PBN];

    const int tid = threadIdx.x;
    const int tx  = tid & 15;        // 0..15 (N direction)
    const int ty  = tid >> 4;        // 0..15 (M direction)
    const int r0  = blockIdx.y * PBM;
    const int n0  = blockIdx.x * PBN;

    const int lr  = tid >> 2;        // 0..63  row within tile for loads
    const int lc4 = (tid & 3) * 4;   // 0,4,8,12  col group

    float c[4][4] = {};

    for (int kt = 0; kt < DM; kt += PBK) {
        float4 av = *(const float4*)&X[(r0 + lr) * DM + kt + lc4];
        float4 wv = *(const float4*)&W[(n0 + lr) * DM + kt + lc4];
        As[(lc4 + 0) * PBM + lr] = av.x;
        As[(lc4 + 1) * PBM + lr] = av.y;
        As[(lc4 + 2) * PBM + lr] = av.z;
        As[(lc4 + 3) * PBM + lr] = av.w;
        Bs[(lc4 + 0) * PBN + lr] = wv.x;
        Bs[(lc4 + 1) * PBN + lr] = wv.y;
        Bs[(lc4 + 2) * PBN + lr] = wv.z;
        Bs[(lc4 + 3) * PBN + lr] = wv.w;
        __syncthreads();

        #pragma unroll
        for (int kk = 0; kk < PBK; kk++) {
            float4 a = *(const float4*)&As[kk * PBM + ty * 4];
            float4 b = *(const float4*)&Bs[kk * PBN + tx * 4];
            float ar[4] = {a.x, a.y, a.z, a.w};
            float br[4] = {b.x, b.y, b.z, b.w};
            #pragma unroll
            for (int i = 0; i < 4; i++)
                #pragma unroll
                for (int j = 0; j < 4; j++)
                    c[i][j] += ar[i] * br[j];
        }
        __syncthreads();
    }

    // Epilogue: add bias, scale, scatter-store into [b,h,s,d].
    const int col = n0 + tx * 4;           // 4 consecutive cols, same head
    float4 bb = *(const float4*)&bias[col];
    const float bbr[4] = {bb.x, bb.y, bb.z, bb.w};
    const int h_ = col >> 6;
    const int dd = col & 63;

    #pragma unroll
    for (int i = 0; i < 4; i++) {
        int r = r0 + ty * 4 + i;
        int b = r >> 11;                   // r / SEQL
        int s = r & (SEQL - 1);
        float4 v;
        v.x = (c[i][0] + bbr[0]) * scale;
        v.y = (c[i][1] + bbr[1]) * scale;
        v.z = (c[i][2] + bbr[2]) * scale;
        v.w = (c[i][3] + bbr[3]) * scale;
        *(float4*)&Out[(((b * H + h_) * SEQL) + s) * D + dd] = v;
    }
}

// ---------------------------------------------------------------------------
// Kernel 2: flash-style attention, fp32, online softmax.
// grid = (SEQL/128, BS*H), block = 128 threads, one thread per query row.
// K/V staged in SMEM in 64-key tiles; all threads walk key j in lockstep so
// all SMEM reads are broadcasts (conflict-free).
// ---------------------------------------------------------------------------
#define AT_ROWS 128
#define KT 64

__global__ __launch_bounds__(128) void attn_kernel(
    const int* __restrict__ mask, float* __restrict__ out)
{
    __shared__ float4 Ks[KT * D / 4];   // 64x64 floats = 16 KB
    __shared__ float4 Vs[KT * D / 4];   // 16 KB
    __shared__ float  biasS[KT];

    const int tid = threadIdx.x;
    const int bh  = blockIdx.y;
    const int b   = bh >> 4;
    const int h_  = bh & 15;
    const int row = blockIdx.x * AT_ROWS + tid;

    // Load this thread's (pre-scaled) q row into registers.
    const float4* Qg = (const float4*)&g_Q[(bh * SEQL + row) * D];
    float4 q[16];
    #pragma unroll
    for (int i = 0; i < 16; i++) q[i] = Qg[i];

    float o[64];
    #pragma unroll
    for (int k = 0; k < 64; k++) o[k] = 0.0f;
    float m = -INFINITY;
    float l = 0.0f;

    for (int kt = 0; kt < SEQL / KT; kt++) {
        const float4* Kg = (const float4*)&g_K[(bh * SEQL + kt * KT) * D];
        const float4* Vg = (const float4*)&g_V[(bh * SEQL + kt * KT) * D];
        __syncthreads();   // previous tile fully consumed
        #pragma unroll
        for (int i = 0; i < 8; i++) {
            Ks[i * 128 + tid] = Kg[i * 128 + tid];
            Vs[i * 128 + tid] = Vg[i * 128 + tid];
        }
        if (tid < KT)
            biasS[tid] = mask[b * SEQL + kt * KT + tid] ? 0.0f : -1e30f;
        __syncthreads();

        #pragma unroll 1
        for (int j = 0; j < KT; j++) {
            // s = q . K[j]  (4 independent chains), plus mask bias
            float a0 = 0.f, a1 = 0.f, a2 = 0.f, a3 = 0.f;
            #pragma unroll
            for (int k4 = 0; k4 < 16; k4++) {
                float4 kv = Ks[j * 16 + k4];   // broadcast across all lanes
                a0 += q[k4].x * kv.x;
                a1 += q[k4].y * kv.y;
                a2 += q[k4].z * kv.z;
                a3 += q[k4].w * kv.w;
            }
            float s = (a0 + a1) + (a2 + a3) + biasS[j];

            // Rare-path rescale: fires ~log(seq) times per row.
            if (s > m) {
                float corr = __expf(m - s);   // first iter: expf(-inf)=0
                m = s;
                l *= corr;
                #pragma unroll
                for (int k = 0; k < 64; k++) o[k] *= corr;
            }
            float p = __expf(s - m);
            l += p;

            #pragma unroll
            for (int k4 = 0; k4 < 16; k4++) {
                float4 vv = Vs[j * 16 + k4];   // broadcast
                o[k4 * 4 + 0] += p * vv.x;
                o[k4 * 4 + 1] += p * vv.y;
                o[k4 * 4 + 2] += p * vv.z;
                o[k4 * 4 + 3] += p * vv.w;
            }
        }
    }

    // Epilogue: normalize and write out[b, s, h*64 + dd].
    const float inv = 1.0f / l;
    float* og = &out[(b * SEQL + row) * DM + h_ * D];
    #pragma unroll
    for (int k4 = 0; k4 < 16; k4++) {
        float4 v;
        v.x = o[k4 * 4 + 0] * inv;
        v.y = o[k4 * 4 + 1] * inv;
        v.z = o[k4 * 4 + 2] * inv;
        v.w = o[k4 * 4 + 3] * inv;
        ((float4*)og)[k4] = v;
    }
}

// ---------------------------------------------------------------------------
extern "C" void kernel_launch(void* const* d_in, const int* in_sizes, int n_in,
                              void* d_out, int out_size)
{
    const float* X    = (const float*)d_in[0];
    const int*   mask = (const int*)  d_in[1];
    const float* Wq   = (const float*)d_in[2];
    const float* bq   = (const float*)d_in[3];
    const float* Wk   = (const float*)d_in[4];
    const float* bk   = (const float*)d_in[5];
    const float* Wv   = (const float*)d_in[6];
    const float* bv   = (const float*)d_in[7];

    dim3 g1(DM / PBN, R / PBM, 3);       // (16, 64, 3)
    qkv_proj_kernel<<<g1, 256>>>(X, Wq, bq, Wk, bk, Wv, bv);

    dim3 g2(SEQL / AT_ROWS, BS * H);     // (16, 32)
    attn_kernel<<<g2, 128>>>(mask, (float*)d_out);
}

// round 6
// speedup vs baseline: 1.2691x; 1.2691x over previous
#include <cuda_runtime.h>
#include <cuda_bf16.h>
#include <math.h>
#include <stdint.h>

#define BS   2
#define SEQL 2048
#define DM   1024
#define H    16
#define D    64
#define R    (BS*SEQL)   // 4096
#define KE   2048        // expanded K (hi|lo) in bf16

// Scratch (__device__ globals — no allocation).
__device__ float g_Q[BS*H*SEQL*D];
__device__ float g_K[BS*H*SEQL*D];
__device__ float g_V[BS*H*SEQL*D];
__device__ __nv_bfloat16 g_Xp[(size_t)R * KE];        // 16 MB
__device__ __nv_bfloat16 g_Wp[(size_t)3 * DM * KE];   // 12 MB

// ===========================================================================
// helpers
// ===========================================================================
__device__ __forceinline__ uint32_t smem_to_u32(const void* p) {
    uint32_t a;
    asm("{ .reg .u64 t; cvta.to.shared.u64 t, %1; cvt.u32.u64 %0, t; }" : "=r"(a) : "l"(p));
    return a;
}
#define SW128(off) ((off) ^ (((off) >> 3) & 0x70))

#define CP_ASYNC16(saddr, gptr) \
    asm volatile("cp.async.cg.shared.global [%0], [%1], 16;" :: "r"(saddr), "l"(gptr))
#define CP_COMMIT() asm volatile("cp.async.commit_group;" ::: "memory")
#define CP_WAIT1()  asm volatile("cp.async.wait_group 1;" ::: "memory")
#define CP_WAIT0()  asm volatile("cp.async.wait_group 0;" ::: "memory")

__device__ __forceinline__ void ldmatrix_x4(uint32_t* r, uint32_t addr) {
    asm volatile("ldmatrix.sync.aligned.m8n8.x4.shared.b16 {%0,%1,%2,%3}, [%4];"
        : "=r"(r[0]), "=r"(r[1]), "=r"(r[2]), "=r"(r[3]) : "r"(addr));
}
__device__ __forceinline__ void mma_bf16(float* d, const uint32_t* a, const uint32_t* b) {
    asm volatile(
        "mma.sync.aligned.m16n8k16.row.col.f32.bf16.bf16.f32 "
        "{%0,%1,%2,%3}, {%4,%5,%6,%7}, {%8,%9}, {%0,%1,%2,%3};"
        : "+f"(d[0]), "+f"(d[1]), "+f"(d[2]), "+f"(d[3])
        : "r"(a[0]), "r"(a[1]), "r"(a[2]), "r"(a[3]), "r"(b[0]), "r"(b[1]));
}

// ===========================================================================
// Split kernel: fp32 [rows, 1024] -> packed bf16 hi|lo:
// dst[r][kblk*64 + 0..31] = hi of k in [kblk*32, kblk*32+32)
// dst[r][kblk*64 + 32..63] = lo
// ===========================================================================
__global__ __launch_bounds__(256) void split_kernel(
    const float* __restrict__ src, __nv_bfloat16* __restrict__ dst)
{
    int idx = blockIdx.x * 256 + threadIdx.x;   // one per 4 elems
    int r = idx >> 8;
    int k = (idx & 255) * 4;
    float4 v = *(const float4*)(src + (size_t)r * DM + k);
    float x[4] = {v.x, v.y, v.z, v.w};
    __nv_bfloat16 hi[4], lo[4];
    #pragma unroll
    for (int i = 0; i < 4; i++) {
        hi[i] = __float2bfloat16(x[i]);
        lo[i] = __float2bfloat16(x[i] - __bfloat162float(hi[i]));
    }
    int kblk = k >> 5, kl = k & 31;
    __nv_bfloat16* base = dst + (size_t)r * KE + kblk * 64 + kl;
    *(__nv_bfloat162*)(base + 0)      = __nv_bfloat162{hi[0], hi[1]};
    *(__nv_bfloat162*)(base + 2)      = __nv_bfloat162{hi[2], hi[3]};
    *(__nv_bfloat162*)(base + 32)     = __nv_bfloat162{lo[0], lo[1]};
    *(__nv_bfloat162*)(base + 34)     = __nv_bfloat162{lo[2], lo[3]};
}

// ===========================================================================
// Projection GEMM via mma.sync bf16, 2-way split (4 cross terms).
// C[m,n] = sum_k X[m,k] * W[n,k];  out = (C + bias) * scale -> [b,h,s,d].
// CTA 128x128, BK=32 original k (= 128B packed row block). cp.async double buf.
// 8 warps: 2(M) x 4(N), warp tile 64x32.
// ===========================================================================
#define BM 128
#define BN 128
#define NK (DM/32)            // 32 iters
#define STAGE_BYTES 32768     // A 16KB + B 16KB

__global__ __launch_bounds__(256, 1) void qkv_mma_kernel(
    const float* __restrict__ bq, const float* __restrict__ bk,
    const float* __restrict__ bv)
{
    extern __shared__ char smem[];
    const uint32_t sbase = smem_to_u32(smem);
    const int tid  = threadIdx.x;
    const int wid  = tid >> 5;
    const int lane = tid & 31;
    const int z    = blockIdx.z;

    const float* bias; float* Out; float scale;
    if (z == 0)      { bias = bq; Out = g_Q; scale = 0.125f; }
    else if (z == 1) { bias = bk; Out = g_K; scale = 1.0f;   }
    else             { bias = bv; Out = g_V; scale = 1.0f;   }

    const int n0 = blockIdx.x * BN;
    const int m0 = blockIdx.y * BM;

    const char* gA = (const char*)g_Xp + (size_t)m0 * 4096;                    // 4096B per row
    const char* gB = (const char*)(g_Wp + (size_t)z * DM * KE) + (size_t)n0 * 4096;

    const int lrow = tid >> 3, lchunk = tid & 7;

    // prologue: stage 0 <- kt 0
    {
        uint32_t sa = sbase, sb = sbase + 16384;
        const char* a = gA + lchunk * 16;
        const char* b = gB + lchunk * 16;
        #pragma unroll
        for (int p = 0; p < 4; p++) {
            int row = lrow + p * 32;
            uint32_t off = SW128((uint32_t)(row * 128 + lchunk * 16));
            CP_ASYNC16(sa + off, a + (size_t)row * 4096);
            CP_ASYNC16(sb + off, b + (size_t)row * 4096);
        }
        CP_COMMIT();
    }

    const int wm = (wid & 1) * 64;
    const int wn = (wid >> 1) * 32;
    float acc[4][4][4];
    #pragma unroll
    for (int f = 0; f < 4; f++)
        #pragma unroll
        for (int g = 0; g < 4; g++)
            #pragma unroll
            for (int i = 0; i < 4; i++) acc[f][g][i] = 0.0f;

    const int lr = lane & 7;        // row within 8x8 matrix
    const int lm = lane >> 3;       // matrix id 0..3 for x4

    for (int kt = 0; kt < NK; kt++) {
        // issue loads for kt+1 into other stage
        if (kt + 1 < NK) {
            int st = (kt + 1) & 1;
            uint32_t sa = sbase + st * STAGE_BYTES, sb = sa + 16384;
            const char* a = gA + (size_t)(kt + 1) * 128 + lchunk * 16;
            const char* b = gB + (size_t)(kt + 1) * 128 + lchunk * 16;
            #pragma unroll
            for (int p = 0; p < 4; p++) {
                int row = lrow + p * 32;
                uint32_t off = SW128((uint32_t)(row * 128 + lchunk * 16));
                CP_ASYNC16(sa + off, a + (size_t)row * 4096);
                CP_ASYNC16(sb + off, b + (size_t)row * 4096);
            }
            CP_COMMIT();
            CP_WAIT1();
        } else {
            CP_WAIT0();
        }
        __syncthreads();

        const uint32_t abase = sbase + (kt & 1) * STAGE_BYTES;
        const uint32_t bbase = abase + 16384;

        #pragma unroll
        for (int kk = 0; kk < 2; kk++) {
            uint32_t af[4][2][4];
            uint32_t bf[4][2][2];
            // A fragments: 4 m-frags x {hi,lo}
            #pragma unroll
            for (int f = 0; f < 4; f++)
                #pragma unroll
                for (int hl = 0; hl < 2; hl++) {
                    int row = wm + f * 16 + lr + ((lm & 1) << 3);
                    int cb  = hl * 64 + kk * 32 + ((lm >> 1) << 4);
                    ldmatrix_x4(af[f][hl], abase + SW128((uint32_t)(row * 128 + cb)));
                }
            // B fragments: 2 n16 groups x {hi,lo} -> 4 n8 frags x {hi,lo}
            #pragma unroll
            for (int g2 = 0; g2 < 2; g2++)
                #pragma unroll
                for (int hl = 0; hl < 2; hl++) {
                    int row = wn + g2 * 16 + lr + ((lm & 1) << 3);
                    int cb  = hl * 64 + kk * 32 + ((lm >> 1) << 4);
                    uint32_t rr[4];
                    ldmatrix_x4(rr, bbase + SW128((uint32_t)(row * 128 + cb)));
                    bf[g2 * 2 + 0][hl][0] = rr[0]; bf[g2 * 2 + 0][hl][1] = rr[2];
                    bf[g2 * 2 + 1][hl][0] = rr[1]; bf[g2 * 2 + 1][hl][1] = rr[3];
                }
            // 4 cross terms: (hiA+loA)*(hiB+loB)
            #pragma unroll
            for (int f = 0; f < 4; f++)
                #pragma unroll
                for (int g = 0; g < 4; g++) {
                    mma_bf16(acc[f][g], af[f][0], bf[g][0]);
                    mma_bf16(acc[f][g], af[f][0], bf[g][1]);
                    mma_bf16(acc[f][g], af[f][1], bf[g][0]);
                    mma_bf16(acc[f][g], af[f][1], bf[g][1]);
                }
        }
        __syncthreads();
    }

    // Epilogue: bias + scale, scatter to [b,h,s,d]
    const int gq = lane >> 2;          // row within frag
    const int gt = lane & 3;           // col pair
    #pragma unroll
    for (int f = 0; f < 4; f++) {
        #pragma unroll
        for (int g = 0; g < 4; g++) {
            int col = n0 + wn + g * 8 + 2 * gt;
            int h_  = col >> 6;
            int dd  = col & 63;
            float b0 = __ldg(&bias[col]), b1 = __ldg(&bias[col + 1]);
            #pragma unroll
            for (int half = 0; half < 2; half++) {
                int m_abs = m0 + wm + f * 16 + gq + half * 8;
                int bb = m_abs >> 11;
                int ss = m_abs & (SEQL - 1);
                float2 v;
                v.x = (acc[f][g][half * 2 + 0] + b0) * scale;
                v.y = (acc[f][g][half * 2 + 1] + b1) * scale;
                *(float2*)&Out[(((size_t)(bb * H + h_) * SEQL) + ss) * D + dd] = v;
            }
        }
    }
}

// ---------------------------------------------------------------------------
// Attention: flash-style fp32, online softmax (unchanged from R1).
// ---------------------------------------------------------------------------
#define AT_ROWS 128
#define KT 64

__global__ __launch_bounds__(128) void attn_kernel(
    const int* __restrict__ mask, float* __restrict__ out)
{
    __shared__ float4 Ks[KT * D / 4];
    __shared__ float4 Vs[KT * D / 4];
    __shared__ float  biasS[KT];

    const int tid = threadIdx.x;
    const int bh  = blockIdx.y;
    const int b   = bh >> 4;
    const int h_  = bh & 15;
    const int row = blockIdx.x * AT_ROWS + tid;

    const float4* Qg = (const float4*)&g_Q[((size_t)bh * SEQL + row) * D];
    float4 q[16];
    #pragma unroll
    for (int i = 0; i < 16; i++) q[i] = Qg[i];

    float o[64];
    #pragma unroll
    for (int k = 0; k < 64; k++) o[k] = 0.0f;
    float m = -INFINITY;
    float l = 0.0f;

    for (int kt = 0; kt < SEQL / KT; kt++) {
        const float4* Kg = (const float4*)&g_K[((size_t)bh * SEQL + kt * KT) * D];
        const float4* Vg = (const float4*)&g_V[((size_t)bh * SEQL + kt * KT) * D];
        __syncthreads();
        #pragma unroll
        for (int i = 0; i < 8; i++) {
            Ks[i * 128 + tid] = Kg[i * 128 + tid];
            Vs[i * 128 + tid] = Vg[i * 128 + tid];
        }
        if (tid < KT)
            biasS[tid] = mask[b * SEQL + kt * KT + tid] ? 0.0f : -1e30f;
        __syncthreads();

        #pragma unroll 1
        for (int j = 0; j < KT; j++) {
            float a0 = 0.f, a1 = 0.f, a2 = 0.f, a3 = 0.f;
            #pragma unroll
            for (int k4 = 0; k4 < 16; k4++) {
                float4 kv = Ks[j * 16 + k4];
                a0 += q[k4].x * kv.x;
                a1 += q[k4].y * kv.y;
                a2 += q[k4].z * kv.z;
                a3 += q[k4].w * kv.w;
            }
            float s = (a0 + a1) + (a2 + a3) + biasS[j];

            if (s > m) {
                float corr = __expf(m - s);
                m = s;
                l *= corr;
                #pragma unroll
                for (int k = 0; k < 64; k++) o[k] *= corr;
            }
            float p = __expf(s - m);
            l += p;

            #pragma unroll
            for (int k4 = 0; k4 < 16; k4++) {
                float4 vv = Vs[j * 16 + k4];
                o[k4 * 4 + 0] += p * vv.x;
                o[k4 * 4 + 1] += p * vv.y;
                o[k4 * 4 + 2] += p * vv.z;
                o[k4 * 4 + 3] += p * vv.w;
            }
        }
    }

    const float inv = 1.0f / l;
    float* og = &out[((size_t)b * SEQL + row) * DM + h_ * D];
    #pragma unroll
    for (int k4 = 0; k4 < 16; k4++) {
        float4 v;
        v.x = o[k4 * 4 + 0] * inv;
        v.y = o[k4 * 4 + 1] * inv;
        v.z = o[k4 * 4 + 2] * inv;
        v.w = o[k4 * 4 + 3] * inv;
        ((float4*)og)[k4] = v;
    }
}

// ---------------------------------------------------------------------------
extern "C" void kernel_launch(void* const* d_in, const int* in_sizes, int n_in,
                              void* d_out, int out_size)
{
    const float* X    = (const float*)d_in[0];
    const int*   mask = (const int*)  d_in[1];
    const float* Wq   = (const float*)d_in[2];
    const float* bq   = (const float*)d_in[3];
    const float* Wk   = (const float*)d_in[4];
    const float* bk   = (const float*)d_in[5];
    const float* Wv   = (const float*)d_in[6];
    const float* bv   = (const float*)d_in[7];

    // resolve device-symbol addresses (host API, capture-safe)
    __nv_bfloat16* xp; cudaGetSymbolAddress((void**)&xp, g_Xp);
    __nv_bfloat16* wp; cudaGetSymbolAddress((void**)&wp, g_Wp);

    // 1) split fp32 -> bf16 hi|lo packed
    split_kernel<<<R, 256>>>(X, xp);                       // 4096 blocks
    split_kernel<<<DM, 256>>>(Wq, wp + (size_t)0 * DM * KE);
    split_kernel<<<DM, 256>>>(Wk, wp + (size_t)1 * DM * KE);
    split_kernel<<<DM, 256>>>(Wv, wp + (size_t)2 * DM * KE);

    // 2) QKV projection GEMMs on tensor cores
    cudaFuncSetAttribute(qkv_mma_kernel,
                         cudaFuncAttributeMaxDynamicSharedMemorySize, 2 * STAGE_BYTES);
    dim3 g1(DM / BN, R / BM, 3);                           // (8, 32, 3)
    qkv_mma_kernel<<<g1, 256, 2 * STAGE_BYTES>>>(bq, bk, bv);

    // 3) attention
    dim3 g2(SEQL / AT_ROWS, BS * H);                       // (16, 32)
    attn_kernel<<<g2, 128>>>(mask, (float*)d_out);
}

// round 7
// speedup vs baseline: 3.2209x; 2.5379x over previous
#include <cuda_runtime.h>
#include <cuda_bf16.h>
#include <math.h>
#include <stdint.h>

#define BS   2
#define SEQL 2048
#define DM   1024
#define H    16
#define D    64
#define R    (BS*SEQL)   // 4096
#define KE   2048        // expanded K (hi|lo) in bf16
#define NBH  (BS*H)      // 32

// Scratch (__device__ globals — no allocation).
// Q/K/V in split-bf16 packed layout: [bh][seq][128] where per 32-d block:
// cols [dblk*64 .. +31] = hi, [dblk*64+32 .. +63] = lo. Row = 256 B.
__device__ __nv_bfloat16 g_Qs[(size_t)NBH*SEQL*128];
__device__ __nv_bfloat16 g_Ks[(size_t)NBH*SEQL*128];
__device__ __nv_bfloat16 g_Vs[(size_t)NBH*SEQL*128];
__device__ __nv_bfloat16 g_Xp[(size_t)R * KE];        // 16 MB
__device__ __nv_bfloat16 g_Wp[(size_t)3 * DM * KE];   // 12 MB

// ===========================================================================
// helpers
// ===========================================================================
__device__ __forceinline__ uint32_t smem_to_u32(const void* p) {
    uint32_t a;
    asm("{ .reg .u64 t; cvta.to.shared.u64 t, %1; cvt.u32.u64 %0, t; }" : "=r"(a) : "l"(p));
    return a;
}
#define SW128(off) ((off) ^ (((off) >> 3) & 0x70))     // 128B rows
#define SWZ256(off) ((off) ^ (((off) >> 4) & 0x70))    // 256B rows

#define CP_ASYNC16(saddr, gptr) \
    asm volatile("cp.async.cg.shared.global [%0], [%1], 16;" :: "r"(saddr), "l"(gptr))
#define CP_COMMIT() asm volatile("cp.async.commit_group;" ::: "memory")
#define CP_WAIT1()  asm volatile("cp.async.wait_group 1;" ::: "memory")
#define CP_WAIT0()  asm volatile("cp.async.wait_group 0;" ::: "memory")

__device__ __forceinline__ void ldmatrix_x4(uint32_t* r, uint32_t addr) {
    asm volatile("ldmatrix.sync.aligned.m8n8.x4.shared.b16 {%0,%1,%2,%3}, [%4];"
        : "=r"(r[0]), "=r"(r[1]), "=r"(r[2]), "=r"(r[3]) : "r"(addr));
}
__device__ __forceinline__ void ldmatrix_x4_trans(uint32_t* r, uint32_t addr) {
    asm volatile("ldmatrix.sync.aligned.m8n8.x4.trans.shared.b16 {%0,%1,%2,%3}, [%4];"
        : "=r"(r[0]), "=r"(r[1]), "=r"(r[2]), "=r"(r[3]) : "r"(addr));
}
__device__ __forceinline__ void mma_bf16(float* d, const uint32_t* a, const uint32_t* b) {
    asm volatile(
        "mma.sync.aligned.m16n8k16.row.col.f32.bf16.bf16.f32 "
        "{%0,%1,%2,%3}, {%4,%5,%6,%7}, {%8,%9}, {%0,%1,%2,%3};"
        : "+f"(d[0]), "+f"(d[1]), "+f"(d[2]), "+f"(d[3])
        : "r"(a[0]), "r"(a[1]), "r"(a[2]), "r"(a[3]), "r"(b[0]), "r"(b[1]));
}
__device__ __forceinline__ float ex2(float x) {
    float y; asm("ex2.approx.ftz.f32 %0, %1;" : "=f"(y) : "f"(x)); return y;
}
__device__ __forceinline__ uint32_t packbf2(float a, float b) {
    __nv_bfloat162 t = __floats2bfloat162_rn(a, b);  // a -> low, b -> high
    return *(uint32_t*)&t;
}
#define LOG2E 1.4426950408889634f

// ===========================================================================
// Split kernel: fp32 [rows, 1024] -> packed bf16 hi|lo (for GEMM inputs)
// ===========================================================================
__global__ __launch_bounds__(256) void split_kernel(
    const float* __restrict__ src, __nv_bfloat16* __restrict__ dst)
{
    int idx = blockIdx.x * 256 + threadIdx.x;
    int r = idx >> 8;
    int k = (idx & 255) * 4;
    float4 v = *(const float4*)(src + (size_t)r * DM + k);
    float x[4] = {v.x, v.y, v.z, v.w};
    __nv_bfloat16 hi[4], lo[4];
    #pragma unroll
    for (int i = 0; i < 4; i++) {
        hi[i] = __float2bfloat16(x[i]);
        lo[i] = __float2bfloat16(x[i] - __bfloat162float(hi[i]));
    }
    int kblk = k >> 5, kl = k & 31;
    __nv_bfloat16* base = dst + (size_t)r * KE + kblk * 64 + kl;
    *(__nv_bfloat162*)(base + 0)  = __nv_bfloat162{hi[0], hi[1]};
    *(__nv_bfloat162*)(base + 2)  = __nv_bfloat162{hi[2], hi[3]};
    *(__nv_bfloat162*)(base + 32) = __nv_bfloat162{lo[0], lo[1]};
    *(__nv_bfloat162*)(base + 34) = __nv_bfloat162{lo[2], lo[3]};
}

// ===========================================================================
// Projection GEMM via mma.sync bf16, 2-way split (4 cross terms).
// Epilogue writes split-bf16 Q/K/V directly (Q pre-scaled by 0.125).
// ===========================================================================
#define BM 128
#define BN 128
#define NK (DM/32)
#define STAGE_BYTES 32768

__global__ __launch_bounds__(256, 1) void qkv_mma_kernel(
    const float* __restrict__ bq, const float* __restrict__ bk,
    const float* __restrict__ bv)
{
    extern __shared__ char smem[];
    const uint32_t sbase = smem_to_u32(smem);
    const int tid  = threadIdx.x;
    const int wid  = tid >> 5;
    const int lane = tid & 31;
    const int z    = blockIdx.z;

    const float* bias; __nv_bfloat16* Outs; float scale;
    if (z == 0)      { bias = bq; Outs = g_Qs; scale = 0.125f; }
    else if (z == 1) { bias = bk; Outs = g_Ks; scale = 1.0f;   }
    else             { bias = bv; Outs = g_Vs; scale = 1.0f;   }

    const int n0 = blockIdx.x * BN;
    const int m0 = blockIdx.y * BM;

    const char* gA = (const char*)g_Xp + (size_t)m0 * 4096;
    const char* gB = (const char*)(g_Wp + (size_t)z * DM * KE) + (size_t)n0 * 4096;

    const int lrow = tid >> 3, lchunk = tid & 7;

    {   // prologue: stage 0 <- kt 0
        uint32_t sa = sbase, sb = sbase + 16384;
        const char* a = gA + lchunk * 16;
        const char* b = gB + lchunk * 16;
        #pragma unroll
        for (int p = 0; p < 4; p++) {
            int row = lrow + p * 32;
            uint32_t off = SW128((uint32_t)(row * 128 + lchunk * 16));
            CP_ASYNC16(sa + off, a + (size_t)row * 4096);
            CP_ASYNC16(sb + off, b + (size_t)row * 4096);
        }
        CP_COMMIT();
    }

    const int wm = (wid & 1) * 64;
    const int wn = (wid >> 1) * 32;
    float acc[4][4][4];
    #pragma unroll
    for (int f = 0; f < 4; f++)
        #pragma unroll
        for (int g = 0; g < 4; g++)
            #pragma unroll
            for (int i = 0; i < 4; i++) acc[f][g][i] = 0.0f;

    const int lr = lane & 7;
    const int lm = lane >> 3;

    for (int kt = 0; kt < NK; kt++) {
        if (kt + 1 < NK) {
            int st = (kt + 1) & 1;
            uint32_t sa = sbase + st * STAGE_BYTES, sb = sa + 16384;
            const char* a = gA + (size_t)(kt + 1) * 128 + lchunk * 16;
            const char* b = gB + (size_t)(kt + 1) * 128 + lchunk * 16;
            #pragma unroll
            for (int p = 0; p < 4; p++) {
                int row = lrow + p * 32;
                uint32_t off = SW128((uint32_t)(row * 128 + lchunk * 16));
                CP_ASYNC16(sa + off, a + (size_t)row * 4096);
                CP_ASYNC16(sb + off, b + (size_t)row * 4096);
            }
            CP_COMMIT();
            CP_WAIT1();
        } else {
            CP_WAIT0();
        }
        __syncthreads();

        const uint32_t abase = sbase + (kt & 1) * STAGE_BYTES;
        const uint32_t bbase = abase + 16384;

        #pragma unroll
        for (int kk = 0; kk < 2; kk++) {
            uint32_t af[4][2][4];
            uint32_t bf[4][2][2];
            #pragma unroll
            for (int f = 0; f < 4; f++)
                #pragma unroll
                for (int hl = 0; hl < 2; hl++) {
                    int row = wm + f * 16 + lr + ((lm & 1) << 3);
                    int cb  = hl * 64 + kk * 32 + ((lm >> 1) << 4);
                    ldmatrix_x4(af[f][hl], abase + SW128((uint32_t)(row * 128 + cb)));
                }
            #pragma unroll
            for (int g2 = 0; g2 < 2; g2++)
                #pragma unroll
                for (int hl = 0; hl < 2; hl++) {
                    int row = wn + g2 * 16 + lr + ((lm & 1) << 3);
                    int cb  = hl * 64 + kk * 32 + ((lm >> 1) << 4);
                    uint32_t rr[4];
                    ldmatrix_x4(rr, bbase + SW128((uint32_t)(row * 128 + cb)));
                    bf[g2 * 2 + 0][hl][0] = rr[0]; bf[g2 * 2 + 0][hl][1] = rr[2];
                    bf[g2 * 2 + 1][hl][0] = rr[1]; bf[g2 * 2 + 1][hl][1] = rr[3];
                }
            #pragma unroll
            for (int f = 0; f < 4; f++)
                #pragma unroll
                for (int g = 0; g < 4; g++) {
                    mma_bf16(acc[f][g], af[f][0], bf[g][0]);
                    mma_bf16(acc[f][g], af[f][0], bf[g][1]);
                    mma_bf16(acc[f][g], af[f][1], bf[g][0]);
                    mma_bf16(acc[f][g], af[f][1], bf[g][1]);
                }
        }
        __syncthreads();
    }

    // Epilogue: bias + scale, hi/lo split, scatter into [bh][s][128] layout.
    const int gq = lane >> 2;
    const int gt = lane & 3;
    #pragma unroll
    for (int f = 0; f < 4; f++) {
        #pragma unroll
        for (int g = 0; g < 4; g++) {
            int col = n0 + wn + g * 8 + 2 * gt;
            int h_  = col >> 6;
            int dd  = col & 63;
            int dblk = dd >> 5, pos = dd & 31;
            float b0 = __ldg(&bias[col]), b1 = __ldg(&bias[col + 1]);
            #pragma unroll
            for (int half = 0; half < 2; half++) {
                int m_abs = m0 + wm + f * 16 + gq + half * 8;
                int bb = m_abs >> 11;
                int ss = m_abs & (SEQL - 1);
                float vx = (acc[f][g][half * 2 + 0] + b0) * scale;
                float vy = (acc[f][g][half * 2 + 1] + b1) * scale;
                __nv_bfloat16 hx = __float2bfloat16(vx);
                __nv_bfloat16 hy = __float2bfloat16(vy);
                __nv_bfloat16 lx = __float2bfloat16(vx - __bfloat162float(hx));
                __nv_bfloat16 ly = __float2bfloat16(vy - __bfloat162float(hy));
                size_t base = ((size_t)((bb * H + h_) * SEQL + ss)) * 128 + dblk * 64 + pos;
                *(__nv_bfloat162*)(Outs + base)      = __nv_bfloat162{hx, hy};
                *(__nv_bfloat162*)(Outs + base + 32) = __nv_bfloat162{lx, ly};
            }
        }
    }
}

// ===========================================================================
// Attention via mma.sync bf16 split (3 cross terms), flash online softmax.
// CTA: 256 thr (8 warps), 128 q-rows of one bh. Warp w: q rows [16w, 16w+16).
// KT=32 keys/iter, 64 iters, double-buffered K/V via cp.async.
// SMEM: Q 32KB | K 2x8KB | V 2x8KB | bias 8KB = 73728 B.
// ===========================================================================
#define AKT 32
#define ANIT (SEQL/AKT)      // 64
#define SQ_OFF 0
#define SK_OFF 32768
#define SV_OFF 49152
#define SB_OFF 65536
#define ATT_SMEM 73728

__global__ __launch_bounds__(256, 1) void attn_mma_kernel(
    const int* __restrict__ mask, float* __restrict__ out)
{
    extern __shared__ char smem[];
    const uint32_t sbase = smem_to_u32(smem);
    const uint32_t sQ = sbase + SQ_OFF;
    const uint32_t sK = sbase + SK_OFF;
    const uint32_t sV = sbase + SV_OFF;
    float* sbias = (float*)(smem + SB_OFF);

    const int tid  = threadIdx.x;
    const int wid  = tid >> 5;
    const int lane = tid & 31;
    const int gq   = lane >> 2;
    const int gt   = lane & 3;
    const int bh   = blockIdx.y;
    const int b    = bh >> 4;
    const int h_   = bh & 15;
    const int qr0  = blockIdx.x * 128;
    const int qw   = wid * 16;

    const char* Qg = (const char*)(g_Qs + ((size_t)bh * SEQL + qr0) * 128);
    const char* Kg = (const char*)(g_Ks + (size_t)bh * SEQL * 128);
    const char* Vg = (const char*)(g_Vs + (size_t)bh * SEQL * 128);

    // prologue loads: Q (8/thread), K0,V0 (2/thread each) -> commit group 0
    {
        #pragma unroll
        for (int i = 0; i < 8; i++) {
            int idx = tid + i * 256;
            int row = idx >> 4, c = idx & 15;
            CP_ASYNC16(sQ + SWZ256((uint32_t)(row * 256 + c * 16)),
                       Qg + (size_t)row * 256 + c * 16);
        }
        #pragma unroll
        for (int i = 0; i < 2; i++) {
            int idx = tid + i * 256;
            int row = idx >> 4, c = idx & 15;
            uint32_t off = SWZ256((uint32_t)(row * 256 + c * 16));
            CP_ASYNC16(sK + off, Kg + (size_t)row * 256 + c * 16);
            CP_ASYNC16(sV + off, Vg + (size_t)row * 256 + c * 16);
        }
        CP_COMMIT();
        // mask -> bias (log2 domain constant; masked = huge negative)
        #pragma unroll
        for (int i = 0; i < 8; i++) {
            int j = tid + i * 256;
            sbias[j] = mask[b * SEQL + j] ? 0.0f : -2.6e29f;
        }
    }

    uint32_t qf[2][4][4];     // [hi/lo][kstep][regs]
    float oacc[8][4];
    #pragma unroll
    for (int j = 0; j < 8; j++)
        #pragma unroll
        for (int i = 0; i < 4; i++) oacc[j][i] = 0.0f;
    float m0 = -INFINITY, m1 = -INFINITY, l0 = 0.0f, l1 = 0.0f;

    for (int kt = 0; kt < ANIT; kt++) {
        if (kt + 1 < ANIT) {
            uint32_t dstK = sK + ((kt + 1) & 1) * 8192;
            uint32_t dstV = sV + ((kt + 1) & 1) * 8192;
            const char* kg = Kg + (size_t)(kt + 1) * AKT * 256;
            const char* vg = Vg + (size_t)(kt + 1) * AKT * 256;
            #pragma unroll
            for (int i = 0; i < 2; i++) {
                int idx = tid + i * 256;
                int row = idx >> 4, c = idx & 15;
                uint32_t off = SWZ256((uint32_t)(row * 256 + c * 16));
                CP_ASYNC16(dstK + off, kg + (size_t)row * 256 + c * 16);
                CP_ASYNC16(dstV + off, vg + (size_t)row * 256 + c * 16);
            }
            CP_COMMIT();
            CP_WAIT1();
        } else {
            CP_WAIT0();
        }
        __syncthreads();

        if (kt == 0) {   // load Q fragments once
            #pragma unroll
            for (int hl = 0; hl < 2; hl++)
                #pragma unroll
                for (int s = 0; s < 4; s++) {
                    int row = qw + (lane & 15);
                    int cb  = (s >> 1) * 128 + hl * 64 + (s & 1) * 32 + ((lane >> 4) << 4);
                    ldmatrix_x4(qf[hl][s], sQ + SWZ256((uint32_t)(row * 256 + cb)));
                }
        }

        const uint32_t Kst = sK + (kt & 1) * 8192;
        const uint32_t Vst = sV + (kt & 1) * 8192;

        // ---- S = Q . K^T (3 split terms) ----
        float sacc[4][4];
        #pragma unroll
        for (int j = 0; j < 4; j++)
            #pragma unroll
            for (int i = 0; i < 4; i++) sacc[j][i] = 0.0f;

        #pragma unroll
        for (int s = 0; s < 4; s++) {
            int rowb = (lane & 15);
            int cbase = (s >> 1) * 128 + (s & 1) * 32 + ((lane >> 4) << 4);
            uint32_t bhi[4][2], blo[4][2];
            #pragma unroll
            for (int g2 = 0; g2 < 2; g2++) {
                uint32_t rr[4];
                ldmatrix_x4(rr, Kst + SWZ256((uint32_t)((g2 * 16 + rowb) * 256 + cbase)));
                bhi[g2 * 2 + 0][0] = rr[0]; bhi[g2 * 2 + 0][1] = rr[2];
                bhi[g2 * 2 + 1][0] = rr[1]; bhi[g2 * 2 + 1][1] = rr[3];
            }
            #pragma unroll
            for (int j = 0; j < 4; j++) {
                mma_bf16(sacc[j], qf[0][s], bhi[j]);   // q_hi * k_hi
                mma_bf16(sacc[j], qf[1][s], bhi[j]);   // q_lo * k_hi
            }
            #pragma unroll
            for (int g2 = 0; g2 < 2; g2++) {
                uint32_t rr[4];
                ldmatrix_x4(rr, Kst + SWZ256((uint32_t)((g2 * 16 + rowb) * 256 + cbase + 64)));
                blo[g2 * 2 + 0][0] = rr[0]; blo[g2 * 2 + 0][1] = rr[2];
                blo[g2 * 2 + 1][0] = rr[1]; blo[g2 * 2 + 1][1] = rr[3];
            }
            #pragma unroll
            for (int j = 0; j < 4; j++)
                mma_bf16(sacc[j], qf[0][s], blo[j]);   // q_hi * k_lo
        }

        // ---- mask bias + online softmax (log2 domain) ----
        float mx0 = -INFINITY, mx1 = -INFINITY;
        #pragma unroll
        for (int j = 0; j < 4; j++) {
            float2 bb = *(float2*)&sbias[kt * AKT + j * 8 + 2 * gt];
            sacc[j][0] = fmaf(sacc[j][0], LOG2E, bb.x);
            sacc[j][1] = fmaf(sacc[j][1], LOG2E, bb.y);
            sacc[j][2] = fmaf(sacc[j][2], LOG2E, bb.x);
            sacc[j][3] = fmaf(sacc[j][3], LOG2E, bb.y);
            mx0 = fmaxf(mx0, fmaxf(sacc[j][0], sacc[j][1]));
            mx1 = fmaxf(mx1, fmaxf(sacc[j][2], sacc[j][3]));
        }
        mx0 = fmaxf(mx0, __shfl_xor_sync(0xFFFFFFFF, mx0, 1));
        mx0 = fmaxf(mx0, __shfl_xor_sync(0xFFFFFFFF, mx0, 2));
        mx1 = fmaxf(mx1, __shfl_xor_sync(0xFFFFFFFF, mx1, 1));
        mx1 = fmaxf(mx1, __shfl_xor_sync(0xFFFFFFFF, mx1, 2));
        float mn0 = fmaxf(m0, mx0), mn1 = fmaxf(m1, mx1);
        float c0 = ex2(m0 - mn0), c1 = ex2(m1 - mn1);
        m0 = mn0; m1 = mn1;
        l0 *= c0;  l1 *= c1;
        #pragma unroll
        for (int j = 0; j < 8; j++) {
            oacc[j][0] *= c0; oacc[j][1] *= c0;
            oacc[j][2] *= c1; oacc[j][3] *= c1;
        }

        uint32_t phiA[2][4], ploA[2][4];
        float ls0 = 0.0f, ls1 = 0.0f;
        #pragma unroll
        for (int j = 0; j < 4; j++) {
            float p0 = ex2(sacc[j][0] - mn0);
            float p1 = ex2(sacc[j][1] - mn0);
            float p2 = ex2(sacc[j][2] - mn1);
            float p3 = ex2(sacc[j][3] - mn1);
            ls0 += p0 + p1; ls1 += p2 + p3;
            __nv_bfloat16 h0 = __float2bfloat16(p0), h1 = __float2bfloat16(p1);
            __nv_bfloat16 h2 = __float2bfloat16(p2), h3 = __float2bfloat16(p3);
            int t = j >> 1, hf = (j & 1) * 2;
            phiA[t][hf + 0] = packbf2(__bfloat162float(h0), __bfloat162float(h1));
            phiA[t][hf + 1] = packbf2(__bfloat162float(h2), __bfloat162float(h3));
            ploA[t][hf + 0] = packbf2(p0 - __bfloat162float(h0), p1 - __bfloat162float(h1));
            ploA[t][hf + 1] = packbf2(p2 - __bfloat162float(h2), p3 - __bfloat162float(h3));
        }
        l0 += ls0; l1 += ls1;

        // ---- O += P . V (3 split terms), V frags via ldmatrix.trans ----
        #pragma unroll
        for (int t = 0; t < 2; t++) {
            int rowb = t * 16 + (lane & 15);
            uint32_t vhi[8][2], vlo[8][2];
            #pragma unroll
            for (int nc = 0; nc < 4; nc++) {
                int cb = (nc >> 1) * 128 + (nc & 1) * 32 + ((lane >> 4) << 4);
                uint32_t rr[4];
                ldmatrix_x4_trans(rr, Vst + SWZ256((uint32_t)(rowb * 256 + cb)));
                vhi[nc * 2 + 0][0] = rr[0]; vhi[nc * 2 + 0][1] = rr[1];
                vhi[nc * 2 + 1][0] = rr[2]; vhi[nc * 2 + 1][1] = rr[3];
            }
            #pragma unroll
            for (int jn = 0; jn < 8; jn++) {
                mma_bf16(oacc[jn], phiA[t], vhi[jn]);   // P_hi * V_hi
                mma_bf16(oacc[jn], ploA[t], vhi[jn]);   // P_lo * V_hi
            }
            #pragma unroll
            for (int nc = 0; nc < 4; nc++) {
                int cb = (nc >> 1) * 128 + 64 + (nc & 1) * 32 + ((lane >> 4) << 4);
                uint32_t rr[4];
                ldmatrix_x4_trans(rr, Vst + SWZ256((uint32_t)(rowb * 256 + cb)));
                vlo[nc * 2 + 0][0] = rr[0]; vlo[nc * 2 + 0][1] = rr[1];
                vlo[nc * 2 + 1][0] = rr[2]; vlo[nc * 2 + 1][1] = rr[3];
            }
            #pragma unroll
            for (int jn = 0; jn < 8; jn++)
                mma_bf16(oacc[jn], phiA[t], vlo[jn]);   // P_hi * V_lo
        }
        __syncthreads();
    }

    // ---- epilogue: reduce l across quad, normalize, write out ----
    l0 += __shfl_xor_sync(0xFFFFFFFF, l0, 1);
    l0 += __shfl_xor_sync(0xFFFFFFFF, l0, 2);
    l1 += __shfl_xor_sync(0xFFFFFFFF, l1, 1);
    l1 += __shfl_xor_sync(0xFFFFFFFF, l1, 2);
    float inv0 = 1.0f / l0, inv1 = 1.0f / l1;

    int r0 = qr0 + qw + gq;
    int r1 = r0 + 8;
    float* o0 = out + ((size_t)b * SEQL + r0) * DM + h_ * D;
    float* o1 = out + ((size_t)b * SEQL + r1) * DM + h_ * D;
    #pragma unroll
    for (int jn = 0; jn < 8; jn++) {
        int dc = jn * 8 + 2 * gt;
        *(float2*)(o0 + dc) = float2{oacc[jn][0] * inv0, oacc[jn][1] * inv0};
        *(float2*)(o1 + dc) = float2{oacc[jn][2] * inv1, oacc[jn][3] * inv1};
    }
}

// ---------------------------------------------------------------------------
extern "C" void kernel_launch(void* const* d_in, const int* in_sizes, int n_in,
                              void* d_out, int out_size)
{
    const float* X    = (const float*)d_in[0];
    const int*   mask = (const int*)  d_in[1];
    const float* Wq   = (const float*)d_in[2];
    const float* bq   = (const float*)d_in[3];
    const float* Wk   = (const float*)d_in[4];
    const float* bk   = (const float*)d_in[5];
    const float* Wv   = (const float*)d_in[6];
    const float* bv   = (const float*)d_in[7];

    __nv_bfloat16* xp; cudaGetSymbolAddress((void**)&xp, g_Xp);
    __nv_bfloat16* wp; cudaGetSymbolAddress((void**)&wp, g_Wp);

    // 1) split fp32 -> bf16 hi|lo packed (GEMM inputs)
    split_kernel<<<R, 256>>>(X, xp);
    split_kernel<<<DM, 256>>>(Wq, wp + (size_t)0 * DM * KE);
    split_kernel<<<DM, 256>>>(Wk, wp + (size_t)1 * DM * KE);
    split_kernel<<<DM, 256>>>(Wv, wp + (size_t)2 * DM * KE);

    // 2) QKV projection on tensor cores -> split-bf16 Q/K/V
    cudaFuncSetAttribute(qkv_mma_kernel,
                         cudaFuncAttributeMaxDynamicSharedMemorySize, 2 * STAGE_BYTES);
    dim3 g1(DM / BN, R / BM, 3);
    qkv_mma_kernel<<<g1, 256, 2 * STAGE_BYTES>>>(bq, bk, bv);

    // 3) attention on tensor cores
    cudaFuncSetAttribute(attn_mma_kernel,
                         cudaFuncAttributeMaxDynamicSharedMemorySize, ATT_SMEM);
    dim3 g2(SEQL / 128, NBH);
    attn_mma_kernel<<<g2, 256, ATT_SMEM>>>(mask, (float*)d_out);
}

// round 8
// speedup vs baseline: 3.7168x; 1.1540x over previous
#include <cuda_runtime.h>
#include <cuda_bf16.h>
#include <math.h>
#include <stdint.h>

#define BS   2
#define SEQL 2048
#define DM   1024
#define H    16
#define D    64
#define R    (BS*SEQL)   // 4096
#define KE   2048        // expanded K (hi|lo) in bf16
#define NBH  (BS*H)      // 32

// Scratch (__device__ globals — no allocation).
// Q/K/V in split-bf16 packed layout: [bh][seq][128] where per 32-d block:
// cols [dblk*64 .. +31] = hi, [dblk*64+32 .. +63] = lo. Row = 256 B.
__device__ __nv_bfloat16 g_Qs[(size_t)NBH*SEQL*128];
__device__ __nv_bfloat16 g_Ks[(size_t)NBH*SEQL*128];
__device__ __nv_bfloat16 g_Vs[(size_t)NBH*SEQL*128];
__device__ __nv_bfloat16 g_Xp[(size_t)R * KE];        // 16 MB
__device__ __nv_bfloat16 g_Wp[(size_t)3 * DM * KE];   // 12 MB

// ===========================================================================
// helpers
// ===========================================================================
__device__ __forceinline__ uint32_t smem_to_u32(const void* p) {
    uint32_t a;
    asm("{ .reg .u64 t; cvta.to.shared.u64 t, %1; cvt.u32.u64 %0, t; }" : "=r"(a) : "l"(p));
    return a;
}
#define SW128(off) ((off) ^ (((off) >> 3) & 0x70))     // 128B rows
#define SWZ256(off) ((off) ^ (((off) >> 4) & 0x70))    // 256B rows

#define CP_ASYNC16(saddr, gptr) \
    asm volatile("cp.async.cg.shared.global [%0], [%1], 16;" :: "r"(saddr), "l"(gptr))
#define CP_COMMIT() asm volatile("cp.async.commit_group;" ::: "memory")
#define CP_WAIT1()  asm volatile("cp.async.wait_group 1;" ::: "memory")
#define CP_WAIT0()  asm volatile("cp.async.wait_group 0;" ::: "memory")

__device__ __forceinline__ void ldmatrix_x4(uint32_t* r, uint32_t addr) {
    asm volatile("ldmatrix.sync.aligned.m8n8.x4.shared.b16 {%0,%1,%2,%3}, [%4];"
        : "=r"(r[0]), "=r"(r[1]), "=r"(r[2]), "=r"(r[3]) : "r"(addr));
}
__device__ __forceinline__ void ldmatrix_x4_trans(uint32_t* r, uint32_t addr) {
    asm volatile("ldmatrix.sync.aligned.m8n8.x4.trans.shared.b16 {%0,%1,%2,%3}, [%4];"
        : "=r"(r[0]), "=r"(r[1]), "=r"(r[2]), "=r"(r[3]) : "r"(addr));
}
__device__ __forceinline__ void mma_bf16(float* d, const uint32_t* a, const uint32_t* b) {
    asm volatile(
        "mma.sync.aligned.m16n8k16.row.col.f32.bf16.bf16.f32 "
        "{%0,%1,%2,%3}, {%4,%5,%6,%7}, {%8,%9}, {%0,%1,%2,%3};"
        : "+f"(d[0]), "+f"(d[1]), "+f"(d[2]), "+f"(d[3])
        : "r"(a[0]), "r"(a[1]), "r"(a[2]), "r"(a[3]), "r"(b[0]), "r"(b[1]));
}
__device__ __forceinline__ float ex2(float x) {
    float y; asm("ex2.approx.ftz.f32 %0, %1;" : "=f"(y) : "f"(x)); return y;
}
__device__ __forceinline__ uint32_t packbf2(float a, float b) {
    __nv_bfloat162 t = __floats2bfloat162_rn(a, b);
    return *(uint32_t*)&t;
}
#define LOG2E 1.4426950408889634f

// ===========================================================================
// Fused split kernel: one block per source row (X then Wq, Wk, Wv).
// fp32 [1024] -> packed bf16 hi|lo: per 32-k block, [0..31]=hi, [32..63]=lo.
// ===========================================================================
__global__ __launch_bounds__(256) void split_all_kernel(
    const float* __restrict__ X,
    const float* __restrict__ Wq, const float* __restrict__ Wk,
    const float* __restrict__ Wv,
    __nv_bfloat16* __restrict__ Xp, __nv_bfloat16* __restrict__ Wp)
{
    int blk = blockIdx.x;
    const float* src;
    __nv_bfloat16* dstrow;
    if (blk < R) {
        src = X + (size_t)blk * DM;
        dstrow = Xp + (size_t)blk * KE;
    } else {
        int w = blk - R;
        int z = w >> 10;                     // which weight
        int row = w & 1023;
        const float* ws = (z == 0) ? Wq : (z == 1) ? Wk : Wv;
        src = ws + (size_t)row * DM;
        dstrow = Wp + ((size_t)z * DM + row) * KE;
    }
    int k = threadIdx.x * 4;
    float4 v = *(const float4*)(src + k);
    float x[4] = {v.x, v.y, v.z, v.w};
    __nv_bfloat16 hi[4], lo[4];
    #pragma unroll
    for (int i = 0; i < 4; i++) {
        hi[i] = __float2bfloat16(x[i]);
        lo[i] = __float2bfloat16(x[i] - __bfloat162float(hi[i]));
    }
    int kblk = k >> 5, kl = k & 31;
    __nv_bfloat16* base = dstrow + kblk * 64 + kl;
    *(__nv_bfloat162*)(base + 0)  = __nv_bfloat162{hi[0], hi[1]};
    *(__nv_bfloat162*)(base + 2)  = __nv_bfloat162{hi[2], hi[3]};
    *(__nv_bfloat162*)(base + 32) = __nv_bfloat162{lo[0], lo[1]};
    *(__nv_bfloat162*)(base + 34) = __nv_bfloat162{lo[2], lo[3]};
}

// ===========================================================================
// Projection GEMM via mma.sync bf16, 3-term split (hi*hi + lo*hi + hi*lo).
// CTA 128x256, warp tile 64x64 (8 warps: 2M x 4N). BK=32 orig k.
// Double-buffered cp.async. Epilogue writes split-bf16 Q/K/V (Q pre-scaled).
// ===========================================================================
#define BM 128
#define BN 256
#define NK (DM/32)
#define STG_A 16384
#define STG_B 32768
#define STAGE_BYTES (STG_A + STG_B)    // 48KB

__global__ __launch_bounds__(256, 1) void qkv_mma_kernel(
    const float* __restrict__ bq, const float* __restrict__ bk,
    const float* __restrict__ bv)
{
    extern __shared__ char smem[];
    const uint32_t sbase = smem_to_u32(smem);
    const int tid  = threadIdx.x;
    const int wid  = tid >> 5;
    const int lane = tid & 31;
    const int z    = blockIdx.z;

    const float* bias; __nv_bfloat16* Outs; float scale;
    if (z == 0)      { bias = bq; Outs = g_Qs; scale = 0.125f; }
    else if (z == 1) { bias = bk; Outs = g_Ks; scale = 1.0f;   }
    else             { bias = bv; Outs = g_Vs; scale = 1.0f;   }

    const int n0 = blockIdx.x * BN;
    const int m0 = blockIdx.y * BM;

    const char* gA = (const char*)g_Xp + (size_t)m0 * 4096;
    const char* gB = (const char*)(g_Wp + (size_t)z * DM * KE) + (size_t)n0 * 4096;

    const int lrow = tid >> 3, lchunk = tid & 7;   // A: 128rows x 8 chunks

    {   // prologue: stage 0 <- kt 0
        uint32_t sa = sbase, sb = sbase + STG_A;
        const char* a = gA + lchunk * 16;
        const char* b = gB + lchunk * 16;
        #pragma unroll
        for (int p = 0; p < 4; p++) {
            int row = lrow + p * 32;
            uint32_t off = SW128((uint32_t)(row * 128 + lchunk * 16));
            CP_ASYNC16(sa + off, a + (size_t)row * 4096);
        }
        #pragma unroll
        for (int p = 0; p < 8; p++) {
            int row = lrow + p * 32;
            uint32_t off = SW128((uint32_t)(row * 128 + lchunk * 16));
            CP_ASYNC16(sb + off, b + (size_t)row * 4096);
        }
        CP_COMMIT();
    }

    const int wm = (wid & 1) * 64;
    const int wn = (wid >> 1) * 64;
    float acc[4][8][4];
    #pragma unroll
    for (int f = 0; f < 4; f++)
        #pragma unroll
        for (int g = 0; g < 8; g++)
            #pragma unroll
            for (int i = 0; i < 4; i++) acc[f][g][i] = 0.0f;

    const int lr = lane & 7;
    const int lm = lane >> 3;

    for (int kt = 0; kt < NK; kt++) {
        if (kt + 1 < NK) {
            int st = (kt + 1) & 1;
            uint32_t sa = sbase + st * STAGE_BYTES, sb = sa + STG_A;
            const char* a = gA + (size_t)(kt + 1) * 128 + lchunk * 16;
            const char* b = gB + (size_t)(kt + 1) * 128 + lchunk * 16;
            #pragma unroll
            for (int p = 0; p < 4; p++) {
                int row = lrow + p * 32;
                uint32_t off = SW128((uint32_t)(row * 128 + lchunk * 16));
                CP_ASYNC16(sa + off, a + (size_t)row * 4096);
            }
            #pragma unroll
            for (int p = 0; p < 8; p++) {
                int row = lrow + p * 32;
                uint32_t off = SW128((uint32_t)(row * 128 + lchunk * 16));
                CP_ASYNC16(sb + off, b + (size_t)row * 4096);
            }
            CP_COMMIT();
            CP_WAIT1();
        } else {
            CP_WAIT0();
        }
        __syncthreads();

        const uint32_t abase = sbase + (kt & 1) * STAGE_BYTES;
        const uint32_t bbase = abase + STG_A;

        #pragma unroll
        for (int kk = 0; kk < 2; kk++) {
            uint32_t af[4][2][4];     // [mfrag][hi/lo][regs]
            uint32_t bhf[8][2];       // B hi n8-fragments
            uint32_t blf[8][2];       // B lo n8-fragments
            #pragma unroll
            for (int f = 0; f < 4; f++)
                #pragma unroll
                for (int hl = 0; hl < 2; hl++) {
                    int row = wm + f * 16 + lr + ((lm & 1) << 3);
                    int cb  = hl * 64 + kk * 32 + ((lm >> 1) << 4);
                    ldmatrix_x4(af[f][hl], abase + SW128((uint32_t)(row * 128 + cb)));
                }
            #pragma unroll
            for (int g2 = 0; g2 < 4; g2++) {
                int row = wn + g2 * 16 + lr + ((lm & 1) << 3);
                int cb  = kk * 32 + ((lm >> 1) << 4);
                uint32_t rr[4];
                ldmatrix_x4(rr, bbase + SW128((uint32_t)(row * 128 + cb)));
                bhf[g2 * 2 + 0][0] = rr[0]; bhf[g2 * 2 + 0][1] = rr[2];
                bhf[g2 * 2 + 1][0] = rr[1]; bhf[g2 * 2 + 1][1] = rr[3];
                ldmatrix_x4(rr, bbase + SW128((uint32_t)(row * 128 + 64 + cb)));
                blf[g2 * 2 + 0][0] = rr[0]; blf[g2 * 2 + 0][1] = rr[2];
                blf[g2 * 2 + 1][0] = rr[1]; blf[g2 * 2 + 1][1] = rr[3];
            }
            // 3 cross terms
            #pragma unroll
            for (int f = 0; f < 4; f++)
                #pragma unroll
                for (int g = 0; g < 8; g++) {
                    mma_bf16(acc[f][g], af[f][0], bhf[g]);   // hi*hi
                    mma_bf16(acc[f][g], af[f][1], bhf[g]);   // lo*hi
                    mma_bf16(acc[f][g], af[f][0], blf[g]);   // hi*lo
                }
        }
        __syncthreads();
    }

    // Epilogue: bias + scale, hi/lo split, scatter into [bh][s][128] layout.
    const int gq = lane >> 2;
    const int gt = lane & 3;
    #pragma unroll
    for (int f = 0; f < 4; f++) {
        #pragma unroll
        for (int g = 0; g < 8; g++) {
            int col = n0 + wn + g * 8 + 2 * gt;
            int h_  = col >> 6;
            int dd  = col & 63;
            int dblk = dd >> 5, pos = dd & 31;
            float b0 = __ldg(&bias[col]), b1 = __ldg(&bias[col + 1]);
            #pragma unroll
            for (int half = 0; half < 2; half++) {
                int m_abs = m0 + wm + f * 16 + gq + half * 8;
                int bb = m_abs >> 11;
                int ss = m_abs & (SEQL - 1);
                float vx = (acc[f][g][half * 2 + 0] + b0) * scale;
                float vy = (acc[f][g][half * 2 + 1] + b1) * scale;
                __nv_bfloat16 hx = __float2bfloat16(vx);
                __nv_bfloat16 hy = __float2bfloat16(vy);
                __nv_bfloat16 lx = __float2bfloat16(vx - __bfloat162float(hx));
                __nv_bfloat16 ly = __float2bfloat16(vy - __bfloat162float(hy));
                size_t base = ((size_t)((bb * H + h_) * SEQL + ss)) * 128 + dblk * 64 + pos;
                *(__nv_bfloat162*)(Outs + base)      = __nv_bfloat162{hx, hy};
                *(__nv_bfloat162*)(Outs + base + 32) = __nv_bfloat162{lx, ly};
            }
        }
    }
}

// ===========================================================================
// Attention via mma.sync bf16 split (3 cross terms), flash online softmax.
// (unchanged from R7 — proven at ~225us / 458 TF/s)
// ===========================================================================
#define AKT 32
#define ANIT (SEQL/AKT)      // 64
#define SQ_OFF 0
#define SK_OFF 32768
#define SV_OFF 49152
#define SB_OFF 65536
#define ATT_SMEM 73728

__global__ __launch_bounds__(256, 1) void attn_mma_kernel(
    const int* __restrict__ mask, float* __restrict__ out)
{
    extern __shared__ char smem[];
    const uint32_t sbase = smem_to_u32(smem);
    const uint32_t sQ = sbase + SQ_OFF;
    const uint32_t sK = sbase + SK_OFF;
    const uint32_t sV = sbase + SV_OFF;
    float* sbias = (float*)(smem + SB_OFF);

    const int tid  = threadIdx.x;
    const int wid  = tid >> 5;
    const int lane = tid & 31;
    const int gq   = lane >> 2;
    const int gt   = lane & 3;
    const int bh   = blockIdx.y;
    const int b    = bh >> 4;
    const int h_   = bh & 15;
    const int qr0  = blockIdx.x * 128;
    const int qw   = wid * 16;

    const char* Qg = (const char*)(g_Qs + ((size_t)bh * SEQL + qr0) * 128);
    const char* Kg = (const char*)(g_Ks + (size_t)bh * SEQL * 128);
    const char* Vg = (const char*)(g_Vs + (size_t)bh * SEQL * 128);

    {
        #pragma unroll
        for (int i = 0; i < 8; i++) {
            int idx = tid + i * 256;
            int row = idx >> 4, c = idx & 15;
            CP_ASYNC16(sQ + SWZ256((uint32_t)(row * 256 + c * 16)),
                       Qg + (size_t)row * 256 + c * 16);
        }
        #pragma unroll
        for (int i = 0; i < 2; i++) {
            int idx = tid + i * 256;
            int row = idx >> 4, c = idx & 15;
            uint32_t off = SWZ256((uint32_t)(row * 256 + c * 16));
            CP_ASYNC16(sK + off, Kg + (size_t)row * 256 + c * 16);
            CP_ASYNC16(sV + off, Vg + (size_t)row * 256 + c * 16);
        }
        CP_COMMIT();
        #pragma unroll
        for (int i = 0; i < 8; i++) {
            int j = tid + i * 256;
            sbias[j] = mask[b * SEQL + j] ? 0.0f : -2.6e29f;
        }
    }

    uint32_t qf[2][4][4];
    float oacc[8][4];
    #pragma unroll
    for (int j = 0; j < 8; j++)
        #pragma unroll
        for (int i = 0; i < 4; i++) oacc[j][i] = 0.0f;
    float m0 = -INFINITY, m1 = -INFINITY, l0 = 0.0f, l1 = 0.0f;

    for (int kt = 0; kt < ANIT; kt++) {
        if (kt + 1 < ANIT) {
            uint32_t dstK = sK + ((kt + 1) & 1) * 8192;
            uint32_t dstV = sV + ((kt + 1) & 1) * 8192;
            const char* kg = Kg + (size_t)(kt + 1) * AKT * 256;
            const char* vg = Vg + (size_t)(kt + 1) * AKT * 256;
            #pragma unroll
            for (int i = 0; i < 2; i++) {
                int idx = tid + i * 256;
                int row = idx >> 4, c = idx & 15;
                uint32_t off = SWZ256((uint32_t)(row * 256 + c * 16));
                CP_ASYNC16(dstK + off, kg + (size_t)row * 256 + c * 16);
                CP_ASYNC16(dstV + off, vg + (size_t)row * 256 + c * 16);
            }
            CP_COMMIT();
            CP_WAIT1();
        } else {
            CP_WAIT0();
        }
        __syncthreads();

        if (kt == 0) {
            #pragma unroll
            for (int hl = 0; hl < 2; hl++)
                #pragma unroll
                for (int s = 0; s < 4; s++) {
                    int row = qw + (lane & 15);
                    int cb  = (s >> 1) * 128 + hl * 64 + (s & 1) * 32 + ((lane >> 4) << 4);
                    ldmatrix_x4(qf[hl][s], sQ + SWZ256((uint32_t)(row * 256 + cb)));
                }
        }

        const uint32_t Kst = sK + (kt & 1) * 8192;
        const uint32_t Vst = sV + (kt & 1) * 8192;

        float sacc[4][4];
        #pragma unroll
        for (int j = 0; j < 4; j++)
            #pragma unroll
            for (int i = 0; i < 4; i++) sacc[j][i] = 0.0f;

        #pragma unroll
        for (int s = 0; s < 4; s++) {
            int rowb = (lane & 15);
            int cbase = (s >> 1) * 128 + (s & 1) * 32 + ((lane >> 4) << 4);
            uint32_t bhi[4][2], blo[4][2];
            #pragma unroll
            for (int g2 = 0; g2 < 2; g2++) {
                uint32_t rr[4];
                ldmatrix_x4(rr, Kst + SWZ256((uint32_t)((g2 * 16 + rowb) * 256 + cbase)));
                bhi[g2 * 2 + 0][0] = rr[0]; bhi[g2 * 2 + 0][1] = rr[2];
                bhi[g2 * 2 + 1][0] = rr[1]; bhi[g2 * 2 + 1][1] = rr[3];
            }
            #pragma unroll
            for (int j = 0; j < 4; j++) {
                mma_bf16(sacc[j], qf[0][s], bhi[j]);
                mma_bf16(sacc[j], qf[1][s], bhi[j]);
            }
            #pragma unroll
            for (int g2 = 0; g2 < 2; g2++) {
                uint32_t rr[4];
                ldmatrix_x4(rr, Kst + SWZ256((uint32_t)((g2 * 16 + rowb) * 256 + cbase + 64)));
                blo[g2 * 2 + 0][0] = rr[0]; blo[g2 * 2 + 0][1] = rr[2];
                blo[g2 * 2 + 1][0] = rr[1]; blo[g2 * 2 + 1][1] = rr[3];
            }
            #pragma unroll
            for (int j = 0; j < 4; j++)
                mma_bf16(sacc[j], qf[0][s], blo[j]);
        }

        float mx0 = -INFINITY, mx1 = -INFINITY;
        #pragma unroll
        for (int j = 0; j < 4; j++) {
            float2 bb = *(float2*)&sbias[kt * AKT + j * 8 + 2 * gt];
            sacc[j][0] = fmaf(sacc[j][0], LOG2E, bb.x);
            sacc[j][1] = fmaf(sacc[j][1], LOG2E, bb.y);
            sacc[j][2] = fmaf(sacc[j][2], LOG2E, bb.x);
            sacc[j][3] = fmaf(sacc[j][3], LOG2E, bb.y);
            mx0 = fmaxf(mx0, fmaxf(sacc[j][0], sacc[j][1]));
            mx1 = fmaxf(mx1, fmaxf(sacc[j][2], sacc[j][3]));
        }
        mx0 = fmaxf(mx0, __shfl_xor_sync(0xFFFFFFFF, mx0, 1));
        mx0 = fmaxf(mx0, __shfl_xor_sync(0xFFFFFFFF, mx0, 2));
        mx1 = fmaxf(mx1, __shfl_xor_sync(0xFFFFFFFF, mx1, 1));
        mx1 = fmaxf(mx1, __shfl_xor_sync(0xFFFFFFFF, mx1, 2));
        float mn0 = fmaxf(m0, mx0), mn1 = fmaxf(m1, mx1);
        float c0 = ex2(m0 - mn0), c1 = ex2(m1 - mn1);
        m0 = mn0; m1 = mn1;
        l0 *= c0;  l1 *= c1;
        #pragma unroll
        for (int j = 0; j < 8; j++) {
            oacc[j][0] *= c0; oacc[j][1] *= c0;
            oacc[j][2] *= c1; oacc[j][3] *= c1;
        }

        uint32_t phiA[2][4], ploA[2][4];
        float ls0 = 0.0f, ls1 = 0.0f;
        #pragma unroll
        for (int j = 0; j < 4; j++) {
            float p0 = ex2(sacc[j][0] - mn0);
            float p1 = ex2(sacc[j][1] - mn0);
            float p2 = ex2(sacc[j][2] - mn1);
            float p3 = ex2(sacc[j][3] - mn1);
            ls0 += p0 + p1; ls1 += p2 + p3;
            __nv_bfloat16 h0 = __float2bfloat16(p0), h1 = __float2bfloat16(p1);
            __nv_bfloat16 h2 = __float2bfloat16(p2), h3 = __float2bfloat16(p3);
            int t = j >> 1, hf = (j & 1) * 2;
            phiA[t][hf + 0] = packbf2(__bfloat162float(h0), __bfloat162float(h1));
            phiA[t][hf + 1] = packbf2(__bfloat162float(h2), __bfloat162float(h3));
            ploA[t][hf + 0] = packbf2(p0 - __bfloat162float(h0), p1 - __bfloat162float(h1));
            ploA[t][hf + 1] = packbf2(p2 - __bfloat162float(h2), p3 - __bfloat162float(h3));
        }
        l0 += ls0; l1 += ls1;

        #pragma unroll
        for (int t = 0; t < 2; t++) {
            int rowb = t * 16 + (lane & 15);
            uint32_t vhi[8][2], vlo[8][2];
            #pragma unroll
            for (int nc = 0; nc < 4; nc++) {
                int cb = (nc >> 1) * 128 + (nc & 1) * 32 + ((lane >> 4) << 4);
                uint32_t rr[4];
                ldmatrix_x4_trans(rr, Vst + SWZ256((uint32_t)(rowb * 256 + cb)));
                vhi[nc * 2 + 0][0] = rr[0]; vhi[nc * 2 + 0][1] = rr[1];
                vhi[nc * 2 + 1][0] = rr[2]; vhi[nc * 2 + 1][1] = rr[3];
            }
            #pragma unroll
            for (int jn = 0; jn < 8; jn++) {
                mma_bf16(oacc[jn], phiA[t], vhi[jn]);
                mma_bf16(oacc[jn], ploA[t], vhi[jn]);
            }
            #pragma unroll
            for (int nc = 0; nc < 4; nc++) {
                int cb = (nc >> 1) * 128 + 64 + (nc & 1) * 32 + ((lane >> 4) << 4);
                uint32_t rr[4];
                ldmatrix_x4_trans(rr, Vst + SWZ256((uint32_t)(rowb * 256 + cb)));
                vlo[nc * 2 + 0][0] = rr[0]; vlo[nc * 2 + 0][1] = rr[1];
                vlo[nc * 2 + 1][0] = rr[2]; vlo[nc * 2 + 1][1] = rr[3];
            }
            #pragma unroll
            for (int jn = 0; jn < 8; jn++)
                mma_bf16(oacc[jn], phiA[t], vlo[jn]);
        }
        __syncthreads();
    }

    l0 += __shfl_xor_sync(0xFFFFFFFF, l0, 1);
    l0 += __shfl_xor_sync(0xFFFFFFFF, l0, 2);
    l1 += __shfl_xor_sync(0xFFFFFFFF, l1, 1);
    l1 += __shfl_xor_sync(0xFFFFFFFF, l1, 2);
    float inv0 = 1.0f / l0, inv1 = 1.0f / l1;

    int r0 = qr0 + qw + gq;
    int r1 = r0 + 8;
    float* o0 = out + ((size_t)b * SEQL + r0) * DM + h_ * D;
    float* o1 = out + ((size_t)b * SEQL + r1) * DM + h_ * D;
    #pragma unroll
    for (int jn = 0; jn < 8; jn++) {
        int dc = jn * 8 + 2 * gt;
        *(float2*)(o0 + dc) = float2{oacc[jn][0] * inv0, oacc[jn][1] * inv0};
        *(float2*)(o1 + dc) = float2{oacc[jn][2] * inv1, oacc[jn][3] * inv1};
    }
}

// ---------------------------------------------------------------------------
extern "C" void kernel_launch(void* const* d_in, const int* in_sizes, int n_in,
                              void* d_out, int out_size)
{
    const float* X    = (const float*)d_in[0];
    const int*   mask = (const int*)  d_in[1];
    const float* Wq   = (const float*)d_in[2];
    const float* bq   = (const float*)d_in[3];
    const float* Wk   = (const float*)d_in[4];
    const float* bk   = (const float*)d_in[5];
    const float* Wv   = (const float*)d_in[6];
    const float* bv   = (const float*)d_in[7];

    __nv_bfloat16* xp; cudaGetSymbolAddress((void**)&xp, g_Xp);
    __nv_bfloat16* wp; cudaGetSymbolAddress((void**)&wp, g_Wp);

    // 1) fused split: X + 3 weights -> bf16 hi|lo packed
    split_all_kernel<<<R + 3 * DM, 256>>>(X, Wq, Wk, Wv, xp, wp);

    // 2) QKV projection on tensor cores -> split-bf16 Q/K/V
    cudaFuncSetAttribute(qkv_mma_kernel,
                         cudaFuncAttributeMaxDynamicSharedMemorySize, 2 * STAGE_BYTES);
    dim3 g1(DM / BN, R / BM, 3);                           // (4, 32, 3)
    qkv_mma_kernel<<<g1, 256, 2 * STAGE_BYTES>>>(bq, bk, bv);

    // 3) attention on tensor cores
    cudaFuncSetAttribute(attn_mma_kernel,
                         cudaFuncAttributeMaxDynamicSharedMemorySize, ATT_SMEM);
    dim3 g2(SEQL / 128, NBH);
    attn_mma_kernel<<<g2, 256, ATT_SMEM>>>(mask, (float*)d_out);
}

// round 9
// speedup vs baseline: 3.8458x; 1.0347x over previous
#include <cuda_runtime.h>
#include <cuda_bf16.h>
#include <math.h>
#include <stdint.h>

#define BS   2
#define SEQL 2048
#define DM   1024
#define H    16
#define D    64
#define R    (BS*SEQL)   // 4096
#define KE   2048        // expanded K (hi|lo) in bf16
#define NBH  (BS*H)      // 32

// Scratch (__device__ globals — no allocation).
// Q/K/V in split-bf16 packed layout: [bh][seq][128] per 32-d block:
// cols [dblk*64 .. +31] = hi, [dblk*64+32 .. +63] = lo. Row = 256 B.
__device__ __nv_bfloat16 g_Qs[(size_t)NBH*SEQL*128];
__device__ __nv_bfloat16 g_Ks[(size_t)NBH*SEQL*128];
__device__ __nv_bfloat16 g_Vs[(size_t)NBH*SEQL*128];
__device__ __nv_bfloat16 g_Xp[(size_t)R * KE];        // 16 MB
__device__ __nv_bfloat16 g_Wp[(size_t)3 * DM * KE];   // 12 MB

// ===========================================================================
// helpers
// ===========================================================================
__device__ __forceinline__ uint32_t smem_to_u32(const void* p) {
    uint32_t a;
    asm("{ .reg .u64 t; cvta.to.shared.u64 t, %1; cvt.u32.u64 %0, t; }" : "=r"(a) : "l"(p));
    return a;
}
#define SW128(off) ((off) ^ (((off) >> 3) & 0x70))     // 128B rows
#define SWZ256(off) ((off) ^ (((off) >> 4) & 0x70))    // 256B rows

#define CP_ASYNC16(saddr, gptr) \
    asm volatile("cp.async.cg.shared.global [%0], [%1], 16;" :: "r"(saddr), "l"(gptr))
#define CP_COMMIT() asm volatile("cp.async.commit_group;" ::: "memory")
#define CP_WAIT2()  asm volatile("cp.async.wait_group 2;" ::: "memory")
#define CP_WAIT1()  asm volatile("cp.async.wait_group 1;" ::: "memory")
#define CP_WAIT0()  asm volatile("cp.async.wait_group 0;" ::: "memory")

__device__ __forceinline__ void ldmatrix_x4(uint32_t* r, uint32_t addr) {
    asm volatile("ldmatrix.sync.aligned.m8n8.x4.shared.b16 {%0,%1,%2,%3}, [%4];"
        : "=r"(r[0]), "=r"(r[1]), "=r"(r[2]), "=r"(r[3]) : "r"(addr));
}
__device__ __forceinline__ void ldmatrix_x4_trans(uint32_t* r, uint32_t addr) {
    asm volatile("ldmatrix.sync.aligned.m8n8.x4.trans.shared.b16 {%0,%1,%2,%3}, [%4];"
        : "=r"(r[0]), "=r"(r[1]), "=r"(r[2]), "=r"(r[3]) : "r"(addr));
}
__device__ __forceinline__ void mma_bf16(float* d, const uint32_t* a, const uint32_t* b) {
    asm volatile(
        "mma.sync.aligned.m16n8k16.row.col.f32.bf16.bf16.f32 "
        "{%0,%1,%2,%3}, {%4,%5,%6,%7}, {%8,%9}, {%0,%1,%2,%3};"
        : "+f"(d[0]), "+f"(d[1]), "+f"(d[2]), "+f"(d[3])
        : "r"(a[0]), "r"(a[1]), "r"(a[2]), "r"(a[3]), "r"(b[0]), "r"(b[1]));
}
__device__ __forceinline__ float ex2(float x) {
    float y; asm("ex2.approx.ftz.f32 %0, %1;" : "=f"(y) : "f"(x)); return y;
}
__device__ __forceinline__ uint32_t packbf2(float a, float b) {
    __nv_bfloat162 t = __floats2bfloat162_rn(a, b);
    return *(uint32_t*)&t;
}
#define LOG2E 1.4426950408889634f

// ===========================================================================
// Fused split kernel: one block per source row (X then Wq, Wk, Wv).
// ===========================================================================
__global__ __launch_bounds__(256) void split_all_kernel(
    const float* __restrict__ X,
    const float* __restrict__ Wq, const float* __restrict__ Wk,
    const float* __restrict__ Wv,
    __nv_bfloat16* __restrict__ Xp, __nv_bfloat16* __restrict__ Wp)
{
    int blk = blockIdx.x;
    const float* src;
    __nv_bfloat16* dstrow;
    if (blk < R) {
        src = X + (size_t)blk * DM;
        dstrow = Xp + (size_t)blk * KE;
    } else {
        int w = blk - R;
        int z = w >> 10;
        int row = w & 1023;
        const float* ws = (z == 0) ? Wq : (z == 1) ? Wk : Wv;
        src = ws + (size_t)row * DM;
        dstrow = Wp + ((size_t)z * DM + row) * KE;
    }
    int k = threadIdx.x * 4;
    float4 v = *(const float4*)(src + k);
    float x[4] = {v.x, v.y, v.z, v.w};
    __nv_bfloat16 hi[4], lo[4];
    #pragma unroll
    for (int i = 0; i < 4; i++) {
        hi[i] = __float2bfloat16(x[i]);
        lo[i] = __float2bfloat16(x[i] - __bfloat162float(hi[i]));
    }
    int kblk = k >> 5, kl = k & 31;
    __nv_bfloat16* base = dstrow + kblk * 64 + kl;
    *(__nv_bfloat162*)(base + 0)  = __nv_bfloat162{hi[0], hi[1]};
    *(__nv_bfloat162*)(base + 2)  = __nv_bfloat162{hi[2], hi[3]};
    *(__nv_bfloat162*)(base + 32) = __nv_bfloat162{lo[0], lo[1]};
    *(__nv_bfloat162*)(base + 34) = __nv_bfloat162{lo[2], lo[3]};
}

// ===========================================================================
// Projection GEMM via mma.sync bf16, 3-term split (hi*hi + lo*hi + hi*lo).
// CTA 128x128, warp tile 64x32 (8 warps: 2M x 4N), BK=32 orig k.
// 3-stage cp.async pipeline; __launch_bounds__(256,2) -> 2 CTA/SM.
// ===========================================================================
#define BM 128
#define BN 128
#define NK (DM/32)                 // 32
#define STG_BYTES 32768            // A 16KB + B 16KB
#define NSTG 3
#define PROJ_SMEM (NSTG * STG_BYTES)   // 96KB

__device__ __forceinline__ void proj_load_stage(
    uint32_t sbase, int stage, int kt,
    const char* gA, const char* gB, int lrow, int lchunk)
{
    uint32_t sa = sbase + stage * STG_BYTES;
    uint32_t sb = sa + 16384;
    const char* a = gA + (size_t)kt * 128 + lchunk * 16;
    const char* b = gB + (size_t)kt * 128 + lchunk * 16;
    #pragma unroll
    for (int p = 0; p < 4; p++) {
        int row = lrow + p * 32;
        uint32_t off = SW128((uint32_t)(row * 128 + lchunk * 16));
        CP_ASYNC16(sa + off, a + (size_t)row * 4096);
        CP_ASYNC16(sb + off, b + (size_t)row * 4096);
    }
}

__global__ __launch_bounds__(256, 2) void qkv_mma_kernel(
    const float* __restrict__ bq, const float* __restrict__ bk,
    const float* __restrict__ bv)
{
    extern __shared__ char smem[];
    const uint32_t sbase = smem_to_u32(smem);
    const int tid  = threadIdx.x;
    const int wid  = tid >> 5;
    const int lane = tid & 31;
    const int z    = blockIdx.z;

    const float* bias; __nv_bfloat16* Outs; float scale;
    if (z == 0)      { bias = bq; Outs = g_Qs; scale = 0.125f; }
    else if (z == 1) { bias = bk; Outs = g_Ks; scale = 1.0f;   }
    else             { bias = bv; Outs = g_Vs; scale = 1.0f;   }

    const int n0 = blockIdx.x * BN;
    const int m0 = blockIdx.y * BM;

    const char* gA = (const char*)g_Xp + (size_t)m0 * 4096;
    const char* gB = (const char*)(g_Wp + (size_t)z * DM * KE) + (size_t)n0 * 4096;

    const int lrow = tid >> 3, lchunk = tid & 7;

    // prologue: stages 0,1 <- kt 0,1
    proj_load_stage(sbase, 0, 0, gA, gB, lrow, lchunk);
    CP_COMMIT();
    proj_load_stage(sbase, 1, 1, gA, gB, lrow, lchunk);
    CP_COMMIT();

    const int wm = (wid & 1) * 64;
    const int wn = (wid >> 1) * 32;
    float acc[4][4][4];
    #pragma unroll
    for (int f = 0; f < 4; f++)
        #pragma unroll
        for (int g = 0; g < 4; g++)
            #pragma unroll
            for (int i = 0; i < 4; i++) acc[f][g][i] = 0.0f;

    const int lr = lane & 7;
    const int lm = lane >> 3;

    int stage = 0;
    for (int kt = 0; kt < NK; kt++) {
        if (kt) __syncthreads();            // compute kt-1 done -> stage reusable
        if (kt + 2 < NK) {
            int st = stage + 2; if (st >= NSTG) st -= NSTG;
            proj_load_stage(sbase, st, kt + 2, gA, gB, lrow, lchunk);
            CP_COMMIT();
            CP_WAIT2();
        } else if (kt + 1 < NK) {
            CP_WAIT1();
        } else {
            CP_WAIT0();
        }
        __syncthreads();                    // stage 'stage' data visible to all

        const uint32_t abase = sbase + stage * STG_BYTES;
        const uint32_t bbase = abase + 16384;

        #pragma unroll
        for (int kk = 0; kk < 2; kk++) {
            uint32_t af[4][2][4];
            uint32_t bhf[4][2], blf[4][2];
            #pragma unroll
            for (int f = 0; f < 4; f++)
                #pragma unroll
                for (int hl = 0; hl < 2; hl++) {
                    int row = wm + f * 16 + lr + ((lm & 1) << 3);
                    int cb  = hl * 64 + kk * 32 + ((lm >> 1) << 4);
                    ldmatrix_x4(af[f][hl], abase + SW128((uint32_t)(row * 128 + cb)));
                }
            #pragma unroll
            for (int g2 = 0; g2 < 2; g2++) {
                int row = wn + g2 * 16 + lr + ((lm & 1) << 3);
                int cb  = kk * 32 + ((lm >> 1) << 4);
                uint32_t rr[4];
                ldmatrix_x4(rr, bbase + SW128((uint32_t)(row * 128 + cb)));
                bhf[g2 * 2 + 0][0] = rr[0]; bhf[g2 * 2 + 0][1] = rr[2];
                bhf[g2 * 2 + 1][0] = rr[1]; bhf[g2 * 2 + 1][1] = rr[3];
                ldmatrix_x4(rr, bbase + SW128((uint32_t)(row * 128 + 64 + cb)));
                blf[g2 * 2 + 0][0] = rr[0]; blf[g2 * 2 + 0][1] = rr[2];
                blf[g2 * 2 + 1][0] = rr[1]; blf[g2 * 2 + 1][1] = rr[3];
            }
            #pragma unroll
            for (int f = 0; f < 4; f++)
                #pragma unroll
                for (int g = 0; g < 4; g++) {
                    mma_bf16(acc[f][g], af[f][0], bhf[g]);   // hi*hi
                    mma_bf16(acc[f][g], af[f][1], bhf[g]);   // lo*hi
                    mma_bf16(acc[f][g], af[f][0], blf[g]);   // hi*lo
                }
        }
        if (++stage >= NSTG) stage = 0;
    }

    // Epilogue: bias + scale, hi/lo split, scatter into [bh][s][128] layout.
    const int gq = lane >> 2;
    const int gt = lane & 3;
    #pragma unroll
    for (int f = 0; f < 4; f++) {
        #pragma unroll
        for (int g = 0; g < 4; g++) {
            int col = n0 + wn + g * 8 + 2 * gt;
            int h_  = col >> 6;
            int dd  = col & 63;
            int dblk = dd >> 5, pos = dd & 31;
            float b0 = __ldg(&bias[col]), b1 = __ldg(&bias[col + 1]);
            #pragma unroll
            for (int half = 0; half < 2; half++) {
                int m_abs = m0 + wm + f * 16 + gq + half * 8;
                int bb = m_abs >> 11;
                int ss = m_abs & (SEQL - 1);
                float vx = (acc[f][g][half * 2 + 0] + b0) * scale;
                float vy = (acc[f][g][half * 2 + 1] + b1) * scale;
                __nv_bfloat16 hx = __float2bfloat16(vx);
                __nv_bfloat16 hy = __float2bfloat16(vy);
                __nv_bfloat16 lx = __float2bfloat16(vx - __bfloat162float(hx));
                __nv_bfloat16 ly = __float2bfloat16(vy - __bfloat162float(hy));
                size_t base = ((size_t)((bb * H + h_) * SEQL + ss)) * 128 + dblk * 64 + pos;
                *(__nv_bfloat162*)(Outs + base)      = __nv_bfloat162{hx, hy};
                *(__nv_bfloat162*)(Outs + base + 32) = __nv_bfloat162{lx, ly};
            }
        }
    }
}

// ===========================================================================
// Attention via mma.sync bf16 split (3 cross terms), flash online softmax.
// (unchanged from R7/R8 — proven at ~225us)
// ===========================================================================
#define AKT 32
#define ANIT (SEQL/AKT)      // 64
#define SQ_OFF 0
#define SK_OFF 32768
#define SV_OFF 49152
#define SB_OFF 65536
#define ATT_SMEM 73728

__global__ __launch_bounds__(256, 1) void attn_mma_kernel(
    const int* __restrict__ mask, float* __restrict__ out)
{
    extern __shared__ char smem[];
    const uint32_t sbase = smem_to_u32(smem);
    const uint32_t sQ = sbase + SQ_OFF;
    const uint32_t sK = sbase + SK_OFF;
    const uint32_t sV = sbase + SV_OFF;
    float* sbias = (float*)(smem + SB_OFF);

    const int tid  = threadIdx.x;
    const int wid  = tid >> 5;
    const int lane = tid & 31;
    const int gq   = lane >> 2;
    const int gt   = lane & 3;
    const int bh   = blockIdx.y;
    const int b    = bh >> 4;
    const int h_   = bh & 15;
    const int qr0  = blockIdx.x * 128;
    const int qw   = wid * 16;

    const char* Qg = (const char*)(g_Qs + ((size_t)bh * SEQL + qr0) * 128);
    const char* Kg = (const char*)(g_Ks + (size_t)bh * SEQL * 128);
    const char* Vg = (const char*)(g_Vs + (size_t)bh * SEQL * 128);

    {
        #pragma unroll
        for (int i = 0; i < 8; i++) {
            int idx = tid + i * 256;
            int row = idx >> 4, c = idx & 15;
            CP_ASYNC16(sQ + SWZ256((uint32_t)(row * 256 + c * 16)),
                       Qg + (size_t)row * 256 + c * 16);
        }
        #pragma unroll
        for (int i = 0; i < 2; i++) {
            int idx = tid + i * 256;
            int row = idx >> 4, c = idx & 15;
            uint32_t off = SWZ256((uint32_t)(row * 256 + c * 16));
            CP_ASYNC16(sK + off, Kg + (size_t)row * 256 + c * 16);
            CP_ASYNC16(sV + off, Vg + (size_t)row * 256 + c * 16);
        }
        CP_COMMIT();
        #pragma unroll
        for (int i = 0; i < 8; i++) {
            int j = tid + i * 256;
            sbias[j] = mask[b * SEQL + j] ? 0.0f : -2.6e29f;
        }
    }

    uint32_t qf[2][4][4];
    float oacc[8][4];
    #pragma unroll
    for (int j = 0; j < 8; j++)
        #pragma unroll
        for (int i = 0; i < 4; i++) oacc[j][i] = 0.0f;
    float m0 = -INFINITY, m1 = -INFINITY, l0 = 0.0f, l1 = 0.0f;

    for (int kt = 0; kt < ANIT; kt++) {
        if (kt + 1 < ANIT) {
            uint32_t dstK = sK + ((kt + 1) & 1) * 8192;
            uint32_t dstV = sV + ((kt + 1) & 1) * 8192;
            const char* kg = Kg + (size_t)(kt + 1) * AKT * 256;
            const char* vg = Vg + (size_t)(kt + 1) * AKT * 256;
            #pragma unroll
            for (int i = 0; i < 2; i++) {
                int idx = tid + i * 256;
                int row = idx >> 4, c = idx & 15;
                uint32_t off = SWZ256((uint32_t)(row * 256 + c * 16));
                CP_ASYNC16(dstK + off, kg + (size_t)row * 256 + c * 16);
                CP_ASYNC16(dstV + off, vg + (size_t)row * 256 + c * 16);
            }
            CP_COMMIT();
            CP_WAIT1();
        } else {
            CP_WAIT0();
        }
        __syncthreads();

        if (kt == 0) {
            #pragma unroll
            for (int hl = 0; hl < 2; hl++)
                #pragma unroll
                for (int s = 0; s < 4; s++) {
                    int row = qw + (lane & 15);
                    int cb  = (s >> 1) * 128 + hl * 64 + (s & 1) * 32 + ((lane >> 4) << 4);
                    ldmatrix_x4(qf[hl][s], sQ + SWZ256((uint32_t)(row * 256 + cb)));
                }
        }

        const uint32_t Kst = sK + (kt & 1) * 8192;
        const uint32_t Vst = sV + (kt & 1) * 8192;

        float sacc[4][4];
        #pragma unroll
        for (int j = 0; j < 4; j++)
            #pragma unroll
            for (int i = 0; i < 4; i++) sacc[j][i] = 0.0f;

        #pragma unroll
        for (int s = 0; s < 4; s++) {
            int rowb = (lane & 15);
            int cbase = (s >> 1) * 128 + (s & 1) * 32 + ((lane >> 4) << 4);
            uint32_t bhi[4][2], blo[4][2];
            #pragma unroll
            for (int g2 = 0; g2 < 2; g2++) {
                uint32_t rr[4];
                ldmatrix_x4(rr, Kst + SWZ256((uint32_t)((g2 * 16 + rowb) * 256 + cbase)));
                bhi[g2 * 2 + 0][0] = rr[0]; bhi[g2 * 2 + 0][1] = rr[2];
                bhi[g2 * 2 + 1][0] = rr[1]; bhi[g2 * 2 + 1][1] = rr[3];
            }
            #pragma unroll
            for (int j = 0; j < 4; j++) {
                mma_bf16(sacc[j], qf[0][s], bhi[j]);
                mma_bf16(sacc[j], qf[1][s], bhi[j]);
            }
            #pragma unroll
            for (int g2 = 0; g2 < 2; g2++) {
                uint32_t rr[4];
                ldmatrix_x4(rr, Kst + SWZ256((uint32_t)((g2 * 16 + rowb) * 256 + cbase + 64)));
                blo[g2 * 2 + 0][0] = rr[0]; blo[g2 * 2 + 0][1] = rr[2];
                blo[g2 * 2 + 1][0] = rr[1]; blo[g2 * 2 + 1][1] = rr[3];
            }
            #pragma unroll
            for (int j = 0; j < 4; j++)
                mma_bf16(sacc[j], qf[0][s], blo[j]);
        }

        float mx0 = -INFINITY, mx1 = -INFINITY;
        #pragma unroll
        for (int j = 0; j < 4; j++) {
            float2 bb = *(float2*)&sbias[kt * AKT + j * 8 + 2 * gt];
            sacc[j][0] = fmaf(sacc[j][0], LOG2E, bb.x);
            sacc[j][1] = fmaf(sacc[j][1], LOG2E, bb.y);
            sacc[j][2] = fmaf(sacc[j][2], LOG2E, bb.x);
            sacc[j][3] = fmaf(sacc[j][3], LOG2E, bb.y);
            mx0 = fmaxf(mx0, fmaxf(sacc[j][0], sacc[j][1]));
            mx1 = fmaxf(mx1, fmaxf(sacc[j][2], sacc[j][3]));
        }
        mx0 = fmaxf(mx0, __shfl_xor_sync(0xFFFFFFFF, mx0, 1));
        mx0 = fmaxf(mx0, __shfl_xor_sync(0xFFFFFFFF, mx0, 2));
        mx1 = fmaxf(mx1, __shfl_xor_sync(0xFFFFFFFF, mx1, 1));
        mx1 = fmaxf(mx1, __shfl_xor_sync(0xFFFFFFFF, mx1, 2));
        float mn0 = fmaxf(m0, mx0), mn1 = fmaxf(m1, mx1);
        float c0 = ex2(m0 - mn0), c1 = ex2(m1 - mn1);
        m0 = mn0; m1 = mn1;
        l0 *= c0;  l1 *= c1;
        #pragma unroll
        for (int j = 0; j < 8; j++) {
            oacc[j][0] *= c0; oacc[j][1] *= c0;
            oacc[j][2] *= c1; oacc[j][3] *= c1;
        }

        uint32_t phiA[2][4], ploA[2][4];
        float ls0 = 0.0f, ls1 = 0.0f;
        #pragma unroll
        for (int j = 0; j < 4; j++) {
            float p0 = ex2(sacc[j][0] - mn0);
            float p1 = ex2(sacc[j][1] - mn0);
            float p2 = ex2(sacc[j][2] - mn1);
            float p3 = ex2(sacc[j][3] - mn1);
            ls0 += p0 + p1; ls1 += p2 + p3;
            __nv_bfloat16 h0 = __float2bfloat16(p0), h1 = __float2bfloat16(p1);
            __nv_bfloat16 h2 = __float2bfloat16(p2), h3 = __float2bfloat16(p3);
            int t = j >> 1, hf = (j & 1) * 2;
            phiA[t][hf + 0] = packbf2(__bfloat162float(h0), __bfloat162float(h1));
            phiA[t][hf + 1] = packbf2(__bfloat162float(h2), __bfloat162float(h3));
            ploA[t][hf + 0] = packbf2(p0 - __bfloat162float(h0), p1 - __bfloat162float(h1));
            ploA[t][hf + 1] = packbf2(p2 - __bfloat162float(h2), p3 - __bfloat162float(h3));
        }
        l0 += ls0; l1 += ls1;

        #pragma unroll
        for (int t = 0; t < 2; t++) {
            int rowb = t * 16 + (lane & 15);
            uint32_t vhi[8][2], vlo[8][2];
            #pragma unroll
            for (int nc = 0; nc < 4; nc++) {
                int cb = (nc >> 1) * 128 + (nc & 1) * 32 + ((lane >> 4) << 4);
                uint32_t rr[4];
                ldmatrix_x4_trans(rr, Vst + SWZ256((uint32_t)(rowb * 256 + cb)));
                vhi[nc * 2 + 0][0] = rr[0]; vhi[nc * 2 + 0][1] = rr[1];
                vhi[nc * 2 + 1][0] = rr[2]; vhi[nc * 2 + 1][1] = rr[3];
            }
            #pragma unroll
            for (int jn = 0; jn < 8; jn++) {
                mma_bf16(oacc[jn], phiA[t], vhi[jn]);
                mma_bf16(oacc[jn], ploA[t], vhi[jn]);
            }
            #pragma unroll
            for (int nc = 0; nc < 4; nc++) {
                int cb = (nc >> 1) * 128 + 64 + (nc & 1) * 32 + ((lane >> 4) << 4);
                uint32_t rr[4];
                ldmatrix_x4_trans(rr, Vst + SWZ256((uint32_t)(rowb * 256 + cb)));
                vlo[nc * 2 + 0][0] = rr[0]; vlo[nc * 2 + 0][1] = rr[1];
                vlo[nc * 2 + 1][0] = rr[2]; vlo[nc * 2 + 1][1] = rr[3];
            }
            #pragma unroll
            for (int jn = 0; jn < 8; jn++)
                mma_bf16(oacc[jn], phiA[t], vlo[jn]);
        }
        __syncthreads();
    }

    l0 += __shfl_xor_sync(0xFFFFFFFF, l0, 1);
    l0 += __shfl_xor_sync(0xFFFFFFFF, l0, 2);
    l1 += __shfl_xor_sync(0xFFFFFFFF, l1, 1);
    l1 += __shfl_xor_sync(0xFFFFFFFF, l1, 2);
    float inv0 = 1.0f / l0, inv1 = 1.0f / l1;

    int r0 = qr0 + qw + gq;
    int r1 = r0 + 8;
    float* o0 = out + ((size_t)b * SEQL + r0) * DM + h_ * D;
    float* o1 = out + ((size_t)b * SEQL + r1) * DM + h_ * D;
    #pragma unroll
    for (int jn = 0; jn < 8; jn++) {
        int dc = jn * 8 + 2 * gt;
        *(float2*)(o0 + dc) = float2{oacc[jn][0] * inv0, oacc[jn][1] * inv0};
        *(float2*)(o1 + dc) = float2{oacc[jn][2] * inv1, oacc[jn][3] * inv1};
    }
}

// ---------------------------------------------------------------------------
extern "C" void kernel_launch(void* const* d_in, const int* in_sizes, int n_in,
                              void* d_out, int out_size)
{
    const float* X    = (const float*)d_in[0];
    const int*   mask = (const int*)  d_in[1];
    const float* Wq   = (const float*)d_in[2];
    const float* bq   = (const float*)d_in[3];
    const float* Wk   = (const float*)d_in[4];
    const float* bk   = (const float*)d_in[5];
    const float* Wv   = (const float*)d_in[6];
    const float* bv   = (const float*)d_in[7];

    __nv_bfloat16* xp; cudaGetSymbolAddress((void**)&xp, g_Xp);
    __nv_bfloat16* wp; cudaGetSymbolAddress((void**)&wp, g_Wp);

    // 1) fused split: X + 3 weights -> bf16 hi|lo packed
    split_all_kernel<<<R + 3 * DM, 256>>>(X, Wq, Wk, Wv, xp, wp);

    // 2) QKV projection on tensor cores -> split-bf16 Q/K/V
    cudaFuncSetAttribute(qkv_mma_kernel,
                         cudaFuncAttributeMaxDynamicSharedMemorySize, PROJ_SMEM);
    dim3 g1(DM / BN, R / BM, 3);                           // (8, 32, 3)
    qkv_mma_kernel<<<g1, 256, PROJ_SMEM>>>(bq, bk, bv);

    // 3) attention on tensor cores
    cudaFuncSetAttribute(attn_mma_kernel,
                         cudaFuncAttributeMaxDynamicSharedMemorySize, ATT_SMEM);
    dim3 g2(SEQL / 128, NBH);
    attn_mma_kernel<<<g2, 256, ATT_SMEM>>>(mask, (float*)d_out);
}

// round 11
// speedup vs baseline: 4.2513x; 1.1055x over previous
#include <cuda_runtime.h>
#include <cuda_bf16.h>
#include <cuda_fp16.h>
#include <math.h>
#include <stdint.h>

#define BS   2
#define SEQL 2048
#define DM   1024
#define H    16
#define D    64
#define R    (BS*SEQL)   // 4096
#define KE   2048        // expanded K (hi|lo) in fp16 for X
#define NBH  (BS*H)      // 32

// Scratch (__device__ globals — no allocation).
// Q/K/V in split-bf16 packed layout: [bh][seq][128] per 32-d block:
// cols [dblk*64 .. +31] = hi, [dblk*64+32 .. +63] = lo. Row = 256 B.
__device__ __nv_bfloat16 g_Qs[(size_t)NBH*SEQL*128];
__device__ __nv_bfloat16 g_Ks[(size_t)NBH*SEQL*128];
__device__ __nv_bfloat16 g_Vs[(size_t)NBH*SEQL*128];
__device__ __half g_Xp[(size_t)R * KE];               // X hi|lo fp16, 16 MB
__device__ __half g_Wh[(size_t)3 * DM * DM];          // W hi-only fp16, 6 MB

// ===========================================================================
// helpers
// ===========================================================================
__device__ __forceinline__ uint32_t smem_to_u32(const void* p) {
    uint32_t a;
    asm("{ .reg .u64 t; cvta.to.shared.u64 t, %1; cvt.u32.u64 %0, t; }" : "=r"(a) : "l"(p));
    return a;
}
#define SW128(off) ((off) ^ (((off) >> 3) & 0x70))     // 128B rows
#define SWZ256(off) ((off) ^ (((off) >> 4) & 0x70))    // 256B rows

#define CP_ASYNC16(saddr, gptr) \
    asm volatile("cp.async.cg.shared.global [%0], [%1], 16;" :: "r"(saddr), "l"(gptr))
#define CP_COMMIT() asm volatile("cp.async.commit_group;" ::: "memory")
#define CP_WAIT1()  asm volatile("cp.async.wait_group 1;" ::: "memory")
#define CP_WAIT0()  asm volatile("cp.async.wait_group 0;" ::: "memory")

__device__ __forceinline__ void ldmatrix_x4(uint32_t* r, uint32_t addr) {
    asm volatile("ldmatrix.sync.aligned.m8n8.x4.shared.b16 {%0,%1,%2,%3}, [%4];"
        : "=r"(r[0]), "=r"(r[1]), "=r"(r[2]), "=r"(r[3]) : "r"(addr));
}
__device__ __forceinline__ void ldmatrix_x4_trans(uint32_t* r, uint32_t addr) {
    asm volatile("ldmatrix.sync.aligned.m8n8.x4.trans.shared.b16 {%0,%1,%2,%3}, [%4];"
        : "=r"(r[0]), "=r"(r[1]), "=r"(r[2]), "=r"(r[3]) : "r"(addr));
}
__device__ __forceinline__ void mma_bf16(float* d, const uint32_t* a, const uint32_t* b) {
    asm volatile(
        "mma.sync.aligned.m16n8k16.row.col.f32.bf16.bf16.f32 "
        "{%0,%1,%2,%3}, {%4,%5,%6,%7}, {%8,%9}, {%0,%1,%2,%3};"
        : "+f"(d[0]), "+f"(d[1]), "+f"(d[2]), "+f"(d[3])
        : "r"(a[0]), "r"(a[1]), "r"(a[2]), "r"(a[3]), "r"(b[0]), "r"(b[1]));
}
__device__ __forceinline__ void mma_fp16(float* d, const uint32_t* a, const uint32_t* b) {
    asm volatile(
        "mma.sync.aligned.m16n8k16.row.col.f32.f16.f16.f32 "
        "{%0,%1,%2,%3}, {%4,%5,%6,%7}, {%8,%9}, {%0,%1,%2,%3};"
        : "+f"(d[0]), "+f"(d[1]), "+f"(d[2]), "+f"(d[3])
        : "r"(a[0]), "r"(a[1]), "r"(a[2]), "r"(a[3]), "r"(b[0]), "r"(b[1]));
}
__device__ __forceinline__ float ex2(float x) {
    float y; asm("ex2.approx.ftz.f32 %0, %1;" : "=f"(y) : "f"(x)); return y;
}
__device__ __forceinline__ uint32_t packbf2(float a, float b) {
    __nv_bfloat162 t = __floats2bfloat162_rn(a, b);
    return *(uint32_t*)&t;
}
#define LOG2E 1.4426950408889634f

// ===========================================================================
// Fused split kernel.
// X rows -> fp16 hi|lo packed (per 32-k block: [32 hi][32 lo]).
// W rows -> fp16 hi only, plain k-major.
// ===========================================================================
__global__ __launch_bounds__(256) void split_all_kernel(
    const float* __restrict__ X,
    const float* __restrict__ Wq, const float* __restrict__ Wk,
    const float* __restrict__ Wv,
    __half* __restrict__ Xp, __half* __restrict__ Wh)
{
    int blk = blockIdx.x;
    int k = threadIdx.x * 4;
    if (blk < R) {
        const float* src = X + (size_t)blk * DM;
        __half* dstrow = Xp + (size_t)blk * KE;
        float4 v = *(const float4*)(src + k);
        float x[4] = {v.x, v.y, v.z, v.w};
        __half hi[4], lo[4];
        #pragma unroll
        for (int i = 0; i < 4; i++) {
            hi[i] = __float2half_rn(x[i]);
            lo[i] = __float2half_rn(x[i] - __half2float(hi[i]));
        }
        int kblk = k >> 5, kl = k & 31;
        __half* base = dstrow + kblk * 64 + kl;
        *(__half2*)(base + 0)  = __half2{hi[0], hi[1]};
        *(__half2*)(base + 2)  = __half2{hi[2], hi[3]};
        *(__half2*)(base + 32) = __half2{lo[0], lo[1]};
        *(__half2*)(base + 34) = __half2{lo[2], lo[3]};
    } else {
        int w = blk - R;
        int z = w >> 10;
        int row = w & 1023;
        const float* ws = (z == 0) ? Wq : (z == 1) ? Wk : Wv;
        const float* src = ws + (size_t)row * DM;
        __half* dstrow = Wh + ((size_t)z * DM + row) * DM;
        float4 v = *(const float4*)(src + k);
        __half2 h01 = __half2{__float2half_rn(v.x), __float2half_rn(v.y)};
        __half2 h23 = __half2{__float2half_rn(v.z), __float2half_rn(v.w)};
        *(__half2*)(dstrow + k)     = h01;
        *(__half2*)(dstrow + k + 2) = h23;
    }
}

// ===========================================================================
// Projection GEMM via mma.sync fp16, 2-term split: C = (Xhi+Xlo) . Whi^T.
// CTA 128x128, warp tile 64x32 (8 warps: 2M x 4N), BK=64 orig k per stage.
// A stage: 128 rows x 256B (hi|lo, SWZ256). B stage: 128 rows x 128B (SW128).
// 2-stage cp.async double buffer (R8-proven schedule: prefetch kt+1 only).
// ===========================================================================
#define BM 128
#define BN 128
#define NK (DM/64)                   // 16 iterations
#define STG_A 32768
#define STG_B 16384
#define STG_BYTES (STG_A + STG_B)    // 48KB
#define PROJ_SMEM (2 * STG_BYTES)    // 96KB

__device__ __forceinline__ void proj_load_stage(
    uint32_t sbase, int stage, int kt,
    const char* gA, const char* gB, int tid)
{
    uint32_t sa = sbase + stage * STG_BYTES;
    uint32_t sb = sa + STG_A;
    // A: 128 rows x 256B (gmem row stride 4096B), byte offset kt*256
    const char* a = gA + (size_t)kt * 256;
    {
        int row = tid >> 4, c = tid & 15;
        #pragma unroll
        for (int p = 0; p < 8; p++) {
            uint32_t off = SWZ256((uint32_t)((row + p * 16) * 256 + c * 16));
            CP_ASYNC16(sa + off, a + (size_t)(row + p * 16) * 4096 + c * 16);
        }
    }
    // B: 128 rows x 128B (gmem row stride 2048B), byte offset kt*128
    const char* b = gB + (size_t)kt * 128;
    {
        int row = tid >> 3, c = tid & 7;
        #pragma unroll
        for (int p = 0; p < 4; p++) {
            uint32_t off = SW128((uint32_t)((row + p * 32) * 128 + c * 16));
            CP_ASYNC16(sb + off, b + (size_t)(row + p * 32) * 2048 + c * 16);
        }
    }
}

__global__ __launch_bounds__(256, 2) void qkv_mma_kernel(
    const float* __restrict__ bq, const float* __restrict__ bk,
    const float* __restrict__ bv)
{
    extern __shared__ char smem[];
    const uint32_t sbase = smem_to_u32(smem);
    const int tid  = threadIdx.x;
    const int wid  = tid >> 5;
    const int lane = tid & 31;
    const int z    = blockIdx.z;

    const float* bias; __nv_bfloat16* Outs; float scale;
    if (z == 0)      { bias = bq; Outs = g_Qs; scale = 0.125f; }
    else if (z == 1) { bias = bk; Outs = g_Ks; scale = 1.0f;   }
    else             { bias = bv; Outs = g_Vs; scale = 1.0f;   }

    const int n0 = blockIdx.x * BN;
    const int m0 = blockIdx.y * BM;

    const char* gA = (const char*)g_Xp + (size_t)m0 * 4096;
    const char* gB = (const char*)(g_Wh + (size_t)z * DM * DM) + (size_t)n0 * 2048;

    // prologue: stage 0 <- kt 0
    proj_load_stage(sbase, 0, 0, gA, gB, tid);
    CP_COMMIT();

    const int wm = (wid & 1) * 64;
    const int wn = (wid >> 1) * 32;
    float acc[4][4][4];
    #pragma unroll
    for (int f = 0; f < 4; f++)
        #pragma unroll
        for (int g = 0; g < 4; g++)
            #pragma unroll
            for (int i = 0; i < 4; i++) acc[f][g][i] = 0.0f;

    const int lrow16 = lane & 15;
    const int lc16   = (lane >> 4) << 4;

    for (int kt = 0; kt < NK; kt++) {
        // prefetch kt+1 into the OTHER stage (safe: compute kt-1 on that
        // stage finished before the trailing __syncthreads of last iter)
        if (kt + 1 < NK) {
            proj_load_stage(sbase, (kt + 1) & 1, kt + 1, gA, gB, tid);
            CP_COMMIT();
            CP_WAIT1();          // kt's group complete
        } else {
            CP_WAIT0();
        }
        __syncthreads();

        const uint32_t abase = sbase + (kt & 1) * STG_BYTES;
        const uint32_t bbase = abase + STG_A;

        #pragma unroll
        for (int kh = 0; kh < 4; kh++) {      // 4 x k16 per stage (64 k)
            const int acb = (kh >> 1) * 128 + (kh & 1) * 32 + lc16;
            uint32_t af[4][2][4];
            #pragma unroll
            for (int f = 0; f < 4; f++)
                #pragma unroll
                for (int hl = 0; hl < 2; hl++) {
                    int row = wm + f * 16 + lrow16;
                    ldmatrix_x4(af[f][hl],
                        abase + SWZ256((uint32_t)(row * 256 + acb + hl * 64)));
                }
            uint32_t bf[4][2];
            #pragma unroll
            for (int g2 = 0; g2 < 2; g2++) {
                int row = wn + g2 * 16 + lrow16;
                uint32_t rr[4];
                ldmatrix_x4(rr, bbase + SW128((uint32_t)(row * 128 + kh * 32 + lc16)));
                bf[g2 * 2 + 0][0] = rr[0]; bf[g2 * 2 + 0][1] = rr[2];
                bf[g2 * 2 + 1][0] = rr[1]; bf[g2 * 2 + 1][1] = rr[3];
            }
            #pragma unroll
            for (int f = 0; f < 4; f++)
                #pragma unroll
                for (int g = 0; g < 4; g++) {
                    mma_fp16(acc[f][g], af[f][0], bf[g]);   // xhi * whi
                    mma_fp16(acc[f][g], af[f][1], bf[g]);   // xlo * whi
                }
        }
        __syncthreads();   // protect stage kt&1 from next iteration's prefetch
    }

    // Epilogue: bias + scale, hi/lo bf16 split, scatter into [bh][s][128].
    const int gq = lane >> 2;
    const int gt = lane & 3;
    #pragma unroll
    for (int f = 0; f < 4; f++) {
        #pragma unroll
        for (int g = 0; g < 4; g++) {
            int col = n0 + wn + g * 8 + 2 * gt;
            int h_  = col >> 6;
            int dd  = col & 63;
            int dblk = dd >> 5, pos = dd & 31;
            float b0 = __ldg(&bias[col]), b1 = __ldg(&bias[col + 1]);
            #pragma unroll
            for (int half = 0; half < 2; half++) {
                int m_abs = m0 + wm + f * 16 + gq + half * 8;
                int bb = m_abs >> 11;
                int ss = m_abs & (SEQL - 1);
                float vx = (acc[f][g][half * 2 + 0] + b0) * scale;
                float vy = (acc[f][g][half * 2 + 1] + b1) * scale;
                __nv_bfloat16 hx = __float2bfloat16(vx);
                __nv_bfloat16 hy = __float2bfloat16(vy);
                __nv_bfloat16 lx = __float2bfloat16(vx - __bfloat162float(hx));
                __nv_bfloat16 ly = __float2bfloat16(vy - __bfloat162float(hy));
                size_t base = ((size_t)((bb * H + h_) * SEQL + ss)) * 128 + dblk * 64 + pos;
                *(__nv_bfloat162*)(Outs + base)      = __nv_bfloat162{hx, hy};
                *(__nv_bfloat162*)(Outs + base + 32) = __nv_bfloat162{lx, ly};
            }
        }
    }
}

// ===========================================================================
// Attention via mma.sync bf16 split (3 cross terms), flash online softmax.
// (unchanged — proven at ~225us)
// ===========================================================================
#define AKT 32
#define ANIT (SEQL/AKT)      // 64
#define SQ_OFF 0
#define SK_OFF 32768
#define SV_OFF 49152
#define SB_OFF 65536
#define ATT_SMEM 73728

__global__ __launch_bounds__(256, 1) void attn_mma_kernel(
    const int* __restrict__ mask, float* __restrict__ out)
{
    extern __shared__ char smem[];
    const uint32_t sbase = smem_to_u32(smem);
    const uint32_t sQ = sbase + SQ_OFF;
    const uint32_t sK = sbase + SK_OFF;
    const uint32_t sV = sbase + SV_OFF;
    float* sbias = (float*)(smem + SB_OFF);

    const int tid  = threadIdx.x;
    const int wid  = tid >> 5;
    const int lane = tid & 31;
    const int gq   = lane >> 2;
    const int gt   = lane & 3;
    const int bh   = blockIdx.y;
    const int b    = bh >> 4;
    const int h_   = bh & 15;
    const int qr0  = blockIdx.x * 128;
    const int qw   = wid * 16;

    const char* Qg = (const char*)(g_Qs + ((size_t)bh * SEQL + qr0) * 128);
    const char* Kg = (const char*)(g_Ks + (size_t)bh * SEQL * 128);
    const char* Vg = (const char*)(g_Vs + (size_t)bh * SEQL * 128);

    {
        #pragma unroll
        for (int i = 0; i < 8; i++) {
            int idx = tid + i * 256;
            int row = idx >> 4, c = idx & 15;
            CP_ASYNC16(sQ + SWZ256((uint32_t)(row * 256 + c * 16)),
                       Qg + (size_t)row * 256 + c * 16);
        }
        #pragma unroll
        for (int i = 0; i < 2; i++) {
            int idx = tid + i * 256;
            int row = idx >> 4, c = idx & 15;
            uint32_t off = SWZ256((uint32_t)(row * 256 + c * 16));
            CP_ASYNC16(sK + off, Kg + (size_t)row * 256 + c * 16);
            CP_ASYNC16(sV + off, Vg + (size_t)row * 256 + c * 16);
        }
        CP_COMMIT();
        #pragma unroll
        for (int i = 0; i < 8; i++) {
            int j = tid + i * 256;
            sbias[j] = mask[b * SEQL + j] ? 0.0f : -2.6e29f;
        }
    }

    uint32_t qf[2][4][4];
    float oacc[8][4];
    #pragma unroll
    for (int j = 0; j < 8; j++)
        #pragma unroll
        for (int i = 0; i < 4; i++) oacc[j][i] = 0.0f;
    float m0 = -INFINITY, m1 = -INFINITY, l0 = 0.0f, l1 = 0.0f;

    for (int kt = 0; kt < ANIT; kt++) {
        if (kt + 1 < ANIT) {
            uint32_t dstK = sK + ((kt + 1) & 1) * 8192;
            uint32_t dstV = sV + ((kt + 1) & 1) * 8192;
            const char* kg = Kg + (size_t)(kt + 1) * AKT * 256;
            const char* vg = Vg + (size_t)(kt + 1) * AKT * 256;
            #pragma unroll
            for (int i = 0; i < 2; i++) {
                int idx = tid + i * 256;
                int row = idx >> 4, c = idx & 15;
                uint32_t off = SWZ256((uint32_t)(row * 256 + c * 16));
                CP_ASYNC16(dstK + off, kg + (size_t)row * 256 + c * 16);
                CP_ASYNC16(dstV + off, vg + (size_t)row * 256 + c * 16);
            }
            CP_COMMIT();
            CP_WAIT1();
        } else {
            CP_WAIT0();
        }
        __syncthreads();

        if (kt == 0) {
            #pragma unroll
            for (int hl = 0; hl < 2; hl++)
                #pragma unroll
                for (int s = 0; s < 4; s++) {
                    int row = qw + (lane & 15);
                    int cb  = (s >> 1) * 128 + hl * 64 + (s & 1) * 32 + ((lane >> 4) << 4);
                    ldmatrix_x4(qf[hl][s], sQ + SWZ256((uint32_t)(row * 256 + cb)));
                }
        }

        const uint32_t Kst = sK + (kt & 1) * 8192;
        const uint32_t Vst = sV + (kt & 1) * 8192;

        float sacc[4][4];
        #pragma unroll
        for (int j = 0; j < 4; j++)
            #pragma unroll
            for (int i = 0; i < 4; i++) sacc[j][i] = 0.0f;

        #pragma unroll
        for (int s = 0; s < 4; s++) {
            int rowb = (lane & 15);
            int cbase = (s >> 1) * 128 + (s & 1) * 32 + ((lane >> 4) << 4);
            uint32_t bhi[4][2], blo[4][2];
            #pragma unroll
            for (int g2 = 0; g2 < 2; g2++) {
                uint32_t rr[4];
                ldmatrix_x4(rr, Kst + SWZ256((uint32_t)((g2 * 16 + rowb) * 256 + cbase)));
                bhi[g2 * 2 + 0][0] = rr[0]; bhi[g2 * 2 + 0][1] = rr[2];
                bhi[g2 * 2 + 1][0] = rr[1]; bhi[g2 * 2 + 1][1] = rr[3];
            }
            #pragma unroll
            for (int j = 0; j < 4; j++) {
                mma_bf16(sacc[j], qf[0][s], bhi[j]);
                mma_bf16(sacc[j], qf[1][s], bhi[j]);
            }
            #pragma unroll
            for (int g2 = 0; g2 < 2; g2++) {
                uint32_t rr[4];
                ldmatrix_x4(rr, Kst + SWZ256((uint32_t)((g2 * 16 + rowb) * 256 + cbase + 64)));
                blo[g2 * 2 + 0][0] = rr[0]; blo[g2 * 2 + 0][1] = rr[2];
                blo[g2 * 2 + 1][0] = rr[1]; blo[g2 * 2 + 1][1] = rr[3];
            }
            #pragma unroll
            for (int j = 0; j < 4; j++)
                mma_bf16(sacc[j], qf[0][s], blo[j]);
        }

        float mx0 = -INFINITY, mx1 = -INFINITY;
        #pragma unroll
        for (int j = 0; j < 4; j++) {
            float2 bb = *(float2*)&sbias[kt * AKT + j * 8 + 2 * gt];
            sacc[j][0] = fmaf(sacc[j][0], LOG2E, bb.x);
            sacc[j][1] = fmaf(sacc[j][1], LOG2E, bb.y);
            sacc[j][2] = fmaf(sacc[j][2], LOG2E, bb.x);
            sacc[j][3] = fmaf(sacc[j][3], LOG2E, bb.y);
            mx0 = fmaxf(mx0, fmaxf(sacc[j][0], sacc[j][1]));
            mx1 = fmaxf(mx1, fmaxf(sacc[j][2], sacc[j][3]));
        }
        mx0 = fmaxf(mx0, __shfl_xor_sync(0xFFFFFFFF, mx0, 1));
        mx0 = fmaxf(mx0, __shfl_xor_sync(0xFFFFFFFF, mx0, 2));
        mx1 = fmaxf(mx1, __shfl_xor_sync(0xFFFFFFFF, mx1, 1));
        mx1 = fmaxf(mx1, __shfl_xor_sync(0xFFFFFFFF, mx1, 2));
        float mn0 = fmaxf(m0, mx0), mn1 = fmaxf(m1, mx1);
        float c0 = ex2(m0 - mn0), c1 = ex2(m1 - mn1);
        m0 = mn0; m1 = mn1;
        l0 *= c0;  l1 *= c1;
        #pragma unroll
        for (int j = 0; j < 8; j++) {
            oacc[j][0] *= c0; oacc[j][1] *= c0;
            oacc[j][2] *= c1; oacc[j][3] *= c1;
        }

        uint32_t phiA[2][4], ploA[2][4];
        float ls0 = 0.0f, ls1 = 0.0f;
        #pragma unroll
        for (int j = 0; j < 4; j++) {
            float p0 = ex2(sacc[j][0] - mn0);
            float p1 = ex2(sacc[j][1] - mn0);
            float p2 = ex2(sacc[j][2] - mn1);
            float p3 = ex2(sacc[j][3] - mn1);
            ls0 += p0 + p1; ls1 += p2 + p3;
            __nv_bfloat16 h0 = __float2bfloat16(p0), h1 = __float2bfloat16(p1);
            __nv_bfloat16 h2 = __float2bfloat16(p2), h3 = __float2bfloat16(p3);
            int t = j >> 1, hf = (j & 1) * 2;
            phiA[t][hf + 0] = packbf2(__bfloat162float(h0), __bfloat162float(h1));
            phiA[t][hf + 1] = packbf2(__bfloat162float(h2), __bfloat162float(h3));
            ploA[t][hf + 0] = packbf2(p0 - __bfloat162float(h0), p1 - __bfloat162float(h1));
            ploA[t][hf + 1] = packbf2(p2 - __bfloat162float(h2), p3 - __bfloat162float(h3));
        }
        l0 += ls0; l1 += ls1;

        #pragma unroll
        for (int t = 0; t < 2; t++) {
            int rowb = t * 16 + (lane & 15);
            uint32_t vhi[8][2], vlo[8][2];
            #pragma unroll
            for (int nc = 0; nc < 4; nc++) {
                int cb = (nc >> 1) * 128 + (nc & 1) * 32 + ((lane >> 4) << 4);
                uint32_t rr[4];
                ldmatrix_x4_trans(rr, Vst + SWZ256((uint32_t)(rowb * 256 + cb)));
                vhi[nc * 2 + 0][0] = rr[0]; vhi[nc * 2 + 0][1] = rr[1];
                vhi[nc * 2 + 1][0] = rr[2]; vhi[nc * 2 + 1][1] = rr[3];
            }
            #pragma unroll
            for (int jn = 0; jn < 8; jn++) {
                mma_bf16(oacc[jn], phiA[t], vhi[jn]);
                mma_bf16(oacc[jn], ploA[t], vhi[jn]);
            }
            #pragma unroll
            for (int nc = 0; nc < 4; nc++) {
                int cb = (nc >> 1) * 128 + 64 + (nc & 1) * 32 + ((lane >> 4) << 4);
                uint32_t rr[4];
                ldmatrix_x4_trans(rr, Vst + SWZ256((uint32_t)(rowb * 256 + cb)));
                vlo[nc * 2 + 0][0] = rr[0]; vlo[nc * 2 + 0][1] = rr[1];
                vlo[nc * 2 + 1][0] = rr[2]; vlo[nc * 2 + 1][1] = rr[3];
            }
            #pragma unroll
            for (int jn = 0; jn < 8; jn++)
                mma_bf16(oacc[jn], phiA[t], vlo[jn]);
        }
        __syncthreads();
    }

    l0 += __shfl_xor_sync(0xFFFFFFFF, l0, 1);
    l0 += __shfl_xor_sync(0xFFFFFFFF, l0, 2);
    l1 += __shfl_xor_sync(0xFFFFFFFF, l1, 1);
    l1 += __shfl_xor_sync(0xFFFFFFFF, l1, 2);
    float inv0 = 1.0f / l0, inv1 = 1.0f / l1;

    int r0 = qr0 + qw + gq;
    int r1 = r0 + 8;
    float* o0 = out + ((size_t)b * SEQL + r0) * DM + h_ * D;
    float* o1 = out + ((size_t)b * SEQL + r1) * DM + h_ * D;
    #pragma unroll
    for (int jn = 0; jn < 8; jn++) {
        int dc = jn * 8 + 2 * gt;
        *(float2*)(o0 + dc) = float2{oacc[jn][0] * inv0, oacc[jn][1] * inv0};
        *(float2*)(o1 + dc) = float2{oacc[jn][2] * inv1, oacc[jn][3] * inv1};
    }
}

// ---------------------------------------------------------------------------
extern "C" void kernel_launch(void* const* d_in, const int* in_sizes, int n_in,
                              void* d_out, int out_size)
{
    const float* X    = (const float*)d_in[0];
    const int*   mask = (const int*)  d_in[1];
    const float* Wq   = (const float*)d_in[2];
    const float* bq   = (const float*)d_in[3];
    const float* Wk   = (const float*)d_in[4];
    const float* bk   = (const float*)d_in[5];
    const float* Wv   = (const float*)d_in[6];
    const float* bv   = (const float*)d_in[7];

    __half* xp; cudaGetSymbolAddress((void**)&xp, g_Xp);
    __half* wh; cudaGetSymbolAddress((void**)&wh, g_Wh);

    // 1) fused split: X -> fp16 hi|lo, W -> fp16 hi
    split_all_kernel<<<R + 3 * DM, 256>>>(X, Wq, Wk, Wv, xp, wh);

    // 2) QKV projection on tensor cores (fp16 2-term) -> split-bf16 Q/K/V
    cudaFuncSetAttribute(qkv_mma_kernel,
                         cudaFuncAttributeMaxDynamicSharedMemorySize, PROJ_SMEM);
    dim3 g1(DM / BN, R / BM, 3);                           // (8, 32, 3)
    qkv_mma_kernel<<<g1, 256, PROJ_SMEM>>>(bq, bk, bv);

    // 3) attention on tensor cores (bf16 3-term, unchanged)
    cudaFuncSetAttribute(attn_mma_kernel,
                         cudaFuncAttributeMaxDynamicSharedMemorySize, ATT_SMEM);
    dim3 g2(SEQL / 128, NBH);
    attn_mma_kernel<<<g2, 256, ATT_SMEM>>>(mask, (float*)d_out);
}